// round 6
// baseline (speedup 1.0000x reference)
#include <cuda_runtime.h>
#include <math.h>

#define BB 8
#define CC 64
#define HH 256
#define WW 256
#define THETA 0.7f

#define TILE_X 64
#define CHUNK 8          // input channels per weight-staging chunk
#define SIN_STRIDE 68    // padded row stride (floats); 68 % 4 == 0 -> float4 aligned

typedef unsigned long long u64;

// Scratch (no allocations allowed in kernel_launch)
__device__ float g_pooled[BB * CC];
__device__ float g_attn[BB * CC];
// Packed duplicated weights: [c][oc][10 taps] as float2 (w,w).
// taps 0..8 = 3x3 conv (row-major, prescaled by THETA), tap 9 = edge weight (prescaled by 1-THETA)
__device__ float2 g_wpack2[CC * CC * 10];

// ---------------- f32x2 helpers ----------------
__device__ __forceinline__ u64 pk2(float lo, float hi) {
    u64 r;
    asm("mov.b64 %0, {%1, %2};" : "=l"(r) : "r"(__float_as_uint(lo)), "r"(__float_as_uint(hi)));
    return r;
}
__device__ __forceinline__ u64 fma2(u64 a, u64 b, u64 c) {
    u64 d;
    asm("fma.rn.f32x2 %0, %1, %2, %3;" : "=l"(d) : "l"(a), "l"(b), "l"(c));
    return d;
}
__device__ __forceinline__ void upk2(u64 v, float& lo, float& hi) {
    unsigned int l, h;
    asm("mov.b64 {%0, %1}, %2;" : "=r"(l), "=r"(h) : "l"(v));
    lo = __uint_as_float(l);
    hi = __uint_as_float(h);
}
#define NEG1X2 0xBF800000BF800000ULL
#define ABSMASK 0x7FFFFFFF7FFFFFFFULL

// ---------------------------------------------------------------------------
// Kernel 0: repack weights (prescaled, duplicated into f32x2 pairs), zero GAP
// ---------------------------------------------------------------------------
__global__ void pack_weights_kernel(const float* __restrict__ Wc,
                                    const float* __restrict__ We) {
    int tid = blockIdx.x * blockDim.x + threadIdx.x;   // 4096 threads
    if (tid < BB * CC) g_pooled[tid] = 0.0f;
    if (tid >= CC * CC) return;
    int c  = tid / CC;
    int oc = tid % CC;
    float2* dst = &g_wpack2[(c * CC + oc) * 10];
#pragma unroll
    for (int k = 0; k < 9; k++) {
        float w = THETA * Wc[(oc * CC + c) * 9 + k];
        dst[k] = make_float2(w, w);
    }
    float we = (1.0f - THETA) * We[oc * CC + c];
    dst[9] = make_float2(we, we);
}

// ---------------------------------------------------------------------------
// Kernel 1: fused 3x3 conv + |vertical diff| 1x1 conv + combine + partial GAP
// Block: 64 oc x (2 rows x 64 px). 256 threads. Thread: 4 oc x 2 rows x 4 px,
// computed as packed f32x2 pixel-pairs (fma.rn.f32x2 = 2 FMA/lane).
// ---------------------------------------------------------------------------
__global__ void __launch_bounds__(256, 2)
conv_kernel(const float* __restrict__ x,
            const float* __restrict__ b_conv,
            float* __restrict__ out) {
    extern __shared__ float smem[];
    float* s_in  = smem;                               // 64 ch * 4 rows * 68
    u64*   s_w   = (u64*)(smem + CC * 4 * SIN_STRIDE); // CHUNK c * 64 oc * 10 (dup pairs)
    float* s_red = (float*)(s_w + CHUNK * CC * 10);    // 64

    const int tid = threadIdx.x;
    const int x0  = blockIdx.x * TILE_X;
    const int y0  = blockIdx.y * 2;        // two output rows: y0, y0+1
    const int b   = blockIdx.z;

    // Stage input tile: rows y0-1 .. y0+2, cols x0-1 .. x0+64, all 64 ch (zero-pad)
    const float* xb = x + (size_t)b * CC * HH * WW;
    for (int idx = tid; idx < CC * 4 * 66; idx += 256) {
        int c   = idx / 264;
        int rem = idx % 264;
        int r   = rem / 66;
        int t   = rem % 66;
        int gy  = y0 - 1 + r;
        int gx  = x0 - 1 + t;
        float v = 0.0f;
        if ((unsigned)gy < HH && (unsigned)gx < WW)
            v = xb[(c * HH + gy) * WW + gx];
        s_in[(c * 4 + r) * SIN_STRIDE + t] = v;
    }
    if (tid < CC) s_red[tid] = 0.0f;

    const int px_thr = tid & 15;     // 16 px-groups of 4 px
    const int oc_thr = tid >> 4;     // 16 oc-groups of 4 oc
    const int pxbase = px_thr * 4;
    const int ocbase = oc_thr * 4;

    // acc[oc][row A/B][px-pair], packed f32x2
    u64 acc[4][2][2];
#pragma unroll
    for (int i = 0; i < 4; i++) {
        float bias = THETA * __ldg(&b_conv[ocbase + i]);
        u64 bp = pk2(bias, bias);
        acc[i][0][0] = bp; acc[i][0][1] = bp;
        acc[i][1][0] = bp; acc[i][1][1] = bp;
    }

    const float4* wsrc_all = (const float4*)g_wpack2;   // 5 float4 per (c,oc)
    float4* s_w4 = (float4*)s_w;

    for (int chunk = 0; chunk < CC / CHUNK; chunk++) {
        __syncthreads();
        // stage dup-weight chunk (coalesced float4): CHUNK*64*5 float4
        for (int idx = tid; idx < CHUNK * CC * 5; idx += 256)
            s_w4[idx] = wsrc_all[chunk * (CHUNK * CC * 5) + idx];
        __syncthreads();

#pragma unroll 1
        for (int cl = 0; cl < CHUNK; cl++) {
            const int c = chunk * CHUNK + cl;
            const float* rowp = &s_in[(c * 4) * SIN_STRIDE + pxbase];

            // Load 4 input rows, 6 floats each
            float r[4][6];
#pragma unroll
            for (int rr = 0; rr < 4; rr++) {
                float4 a = *(const float4*)(rowp + rr * SIN_STRIDE);
                float2 bq = *(const float2*)(rowp + rr * SIN_STRIDE + 4);
                r[rr][0] = a.x; r[rr][1] = a.y; r[rr][2] = a.z;
                r[rr][3] = a.w; r[rr][4] = bq.x; r[rr][5] = bq.y;
            }
            // Sliding pixel-pairs p[row][s] = (r[s], r[s+1])
            u64 p[4][5];
#pragma unroll
            for (int rr = 0; rr < 4; rr++) {
                p[rr][0] = pk2(r[rr][0], r[rr][1]);
                p[rr][1] = pk2(r[rr][1], r[rr][2]);
                p[rr][2] = pk2(r[rr][2], r[rr][3]);
                p[rr][3] = pk2(r[rr][3], r[rr][4]);
                p[rr][4] = pk2(r[rr][4], r[rr][5]);
            }
            // |vertical diff| packed: row A uses local rows 0,2; row B uses 1,3
            u64 dA0 = fma2(p[2][1], NEG1X2, p[0][1]) & ABSMASK;  // cols (1,2)
            u64 dA1 = fma2(p[2][3], NEG1X2, p[0][3]) & ABSMASK;  // cols (3,4)
            u64 dB0 = fma2(p[3][1], NEG1X2, p[1][1]) & ABSMASK;
            u64 dB1 = fma2(p[3][3], NEG1X2, p[1][3]) & ABSMASK;

#pragma unroll
            for (int i = 0; i < 4; i++) {
                const ulonglong2* wp =
                    (const ulonglong2*)&s_w[(cl * CC + ocbase + i) * 10];
                ulonglong2 w01 = wp[0];   // taps 0,1
                ulonglong2 w23 = wp[1];   // taps 2,3
                ulonglong2 w45 = wp[2];   // taps 4,5
                ulonglong2 w67 = wp[3];   // taps 6,7
                ulonglong2 w89 = wp[4];   // tap 8, edge

                // tap k = kr*3+kc : rowA operand p[kr][kc+2*jp], rowB p[kr+1][kc+2*jp]
                acc[i][0][0] = fma2(w01.x, p[0][0], acc[i][0][0]);
                acc[i][0][1] = fma2(w01.x, p[0][2], acc[i][0][1]);
                acc[i][1][0] = fma2(w01.x, p[1][0], acc[i][1][0]);
                acc[i][1][1] = fma2(w01.x, p[1][2], acc[i][1][1]);

                acc[i][0][0] = fma2(w01.y, p[0][1], acc[i][0][0]);
                acc[i][0][1] = fma2(w01.y, p[0][3], acc[i][0][1]);
                acc[i][1][0] = fma2(w01.y, p[1][1], acc[i][1][0]);
                acc[i][1][1] = fma2(w01.y, p[1][3], acc[i][1][1]);

                acc[i][0][0] = fma2(w23.x, p[0][2], acc[i][0][0]);
                acc[i][0][1] = fma2(w23.x, p[0][4], acc[i][0][1]);
                acc[i][1][0] = fma2(w23.x, p[1][2], acc[i][1][0]);
                acc[i][1][1] = fma2(w23.x, p[1][4], acc[i][1][1]);

                acc[i][0][0] = fma2(w23.y, p[1][0], acc[i][0][0]);
                acc[i][0][1] = fma2(w23.y, p[1][2], acc[i][0][1]);
                acc[i][1][0] = fma2(w23.y, p[2][0], acc[i][1][0]);
                acc[i][1][1] = fma2(w23.y, p[2][2], acc[i][1][1]);

                acc[i][0][0] = fma2(w45.x, p[1][1], acc[i][0][0]);
                acc[i][0][1] = fma2(w45.x, p[1][3], acc[i][0][1]);
                acc[i][1][0] = fma2(w45.x, p[2][1], acc[i][1][0]);
                acc[i][1][1] = fma2(w45.x, p[2][3], acc[i][1][1]);

                acc[i][0][0] = fma2(w45.y, p[1][2], acc[i][0][0]);
                acc[i][0][1] = fma2(w45.y, p[1][4], acc[i][0][1]);
                acc[i][1][0] = fma2(w45.y, p[2][2], acc[i][1][0]);
                acc[i][1][1] = fma2(w45.y, p[2][4], acc[i][1][1]);

                acc[i][0][0] = fma2(w67.x, p[2][0], acc[i][0][0]);
                acc[i][0][1] = fma2(w67.x, p[2][2], acc[i][0][1]);
                acc[i][1][0] = fma2(w67.x, p[3][0], acc[i][1][0]);
                acc[i][1][1] = fma2(w67.x, p[3][2], acc[i][1][1]);

                acc[i][0][0] = fma2(w67.y, p[2][1], acc[i][0][0]);
                acc[i][0][1] = fma2(w67.y, p[2][3], acc[i][0][1]);
                acc[i][1][0] = fma2(w67.y, p[3][1], acc[i][1][0]);
                acc[i][1][1] = fma2(w67.y, p[3][3], acc[i][1][1]);

                acc[i][0][0] = fma2(w89.x, p[2][2], acc[i][0][0]);
                acc[i][0][1] = fma2(w89.x, p[2][4], acc[i][0][1]);
                acc[i][1][0] = fma2(w89.x, p[3][2], acc[i][1][0]);
                acc[i][1][1] = fma2(w89.x, p[3][4], acc[i][1][1]);

                acc[i][0][0] = fma2(w89.y, dA0, acc[i][0][0]);
                acc[i][0][1] = fma2(w89.y, dA1, acc[i][0][1]);
                acc[i][1][0] = fma2(w89.y, dB0, acc[i][1][0]);
                acc[i][1][1] = fma2(w89.y, dB1, acc[i][1][1]);
            }
        }
    }

    // Unpack, store (float4 coalesced), and accumulate GAP partials
#pragma unroll
    for (int i = 0; i < 4; i++) {
        const int oc = ocbase + i;
        float sum = 0.0f;
#pragma unroll
        for (int rsel = 0; rsel < 2; rsel++) {
            float4 v;
            upk2(acc[i][rsel][0], v.x, v.y);
            upk2(acc[i][rsel][1], v.z, v.w);
            *(float4*)&out[(((size_t)b * CC + oc) * HH + (y0 + rsel)) * WW + x0 + pxbase] = v;
            sum += v.x + v.y + v.z + v.w;
        }
        atomicAdd(&s_red[oc], sum);
    }
    __syncthreads();
    if (tid < CC) atomicAdd(&g_pooled[b * CC + tid], s_red[tid]);
}

// ---------------------------------------------------------------------------
// Kernel 2: SE attention (GAP -> 1x1 -> ReLU -> 1x1 -> sigmoid), 1 block
// ---------------------------------------------------------------------------
__global__ void attn_kernel(const float* __restrict__ W1, const float* __restrict__ b1,
                            const float* __restrict__ W2, const float* __restrict__ b2) {
    __shared__ float sh[BB * 8];
    const int t = threadIdx.x;
    if (t < BB * 8) {
        int b = t >> 3, r = t & 7;
        float s = b1[r];
        const float inv = 1.0f / (float)(HH * WW);
#pragma unroll
        for (int c = 0; c < CC; c++)
            s += (g_pooled[b * CC + c] * inv) * W1[r * CC + c];
        sh[t] = fmaxf(s, 0.0f);
    }
    __syncthreads();
    for (int idx = t; idx < BB * CC; idx += 256) {
        int b = idx >> 6, o = idx & 63;
        float s = b2[o];
#pragma unroll
        for (int r = 0; r < 8; r++)
            s += sh[b * 8 + r] * W2[o * 8 + r];
        g_attn[idx] = 1.0f / (1.0f + expf(-s));
    }
}

// ---------------------------------------------------------------------------
// Kernel 3: scale output by per-(b,c) attention (float4 grid)
// ---------------------------------------------------------------------------
__global__ void scale_kernel(float* __restrict__ out) {
    int i = blockIdx.x * blockDim.x + threadIdx.x;   // exactly B*C*H*W/4 threads
    float4 v = ((float4*)out)[i];
    float a = g_attn[i >> 14];                       // 65536/4 float4 per (b,c)
    v.x *= a; v.y *= a; v.z *= a; v.w *= a;
    ((float4*)out)[i] = v;
}

// ---------------------------------------------------------------------------
extern "C" void kernel_launch(void* const* d_in, const int* in_sizes, int n_in,
                              void* d_out, int out_size) {
    const float* x  = (const float*)d_in[0];
    const float* Wc = (const float*)d_in[1];
    const float* bc = (const float*)d_in[2];
    const float* We = (const float*)d_in[3];
    const float* W1 = (const float*)d_in[4];
    const float* b1 = (const float*)d_in[5];
    const float* W2 = (const float*)d_in[6];
    const float* b2 = (const float*)d_in[7];
    float* out = (float*)d_out;

    // 69632 (input) + 40960 (dup weights) + 256 (reduction) = 110848 bytes
    const int smem_bytes = CC * 4 * SIN_STRIDE * 4 + CHUNK * CC * 10 * 8 + CC * 4;
    cudaFuncSetAttribute(conv_kernel, cudaFuncAttributeMaxDynamicSharedMemorySize, smem_bytes);

    pack_weights_kernel<<<16, 256>>>(Wc, We);

    dim3 grid(WW / TILE_X, HH / 2, BB);
    conv_kernel<<<grid, 256, smem_bytes>>>(x, bc, out);

    attn_kernel<<<1, 256>>>(W1, b1, W2, b2);

    scale_kernel<<<(BB * CC * HH * WW / 4) / 256, 256>>>(out);
}

// round 7
// speedup vs baseline: 1.0031x; 1.0031x over previous
#include <cuda_runtime.h>
#include <math.h>

#define BB 8
#define CC 64
#define HH 256
#define WW 256
#define THETA 0.7f

#define TILE_X 64
#define CHUNK 8          // input channels per weight-staging chunk
#define SIN_STRIDE 68    // padded row stride (floats); 68 % 4 == 0 -> float4 aligned

typedef unsigned long long u64;

// Scratch (no allocations allowed in kernel_launch)
__device__ float g_pooled[BB * CC];
__device__ float g_attn[BB * CC];
// Packed duplicated weights: [c][oc][10 taps] as float2 (w,w).
// taps 0..8 = 3x3 conv (row-major, prescaled by THETA), tap 9 = edge weight (prescaled by 1-THETA)
__device__ float2 g_wpack2[CC * CC * 10];

// ---------------- f32x2 helpers ----------------
__device__ __forceinline__ u64 pk2(float lo, float hi) {
    u64 r;
    asm("mov.b64 %0, {%1, %2};" : "=l"(r) : "r"(__float_as_uint(lo)), "r"(__float_as_uint(hi)));
    return r;
}
__device__ __forceinline__ u64 fma2(u64 a, u64 b, u64 c) {
    u64 d;
    asm("fma.rn.f32x2 %0, %1, %2, %3;" : "=l"(d) : "l"(a), "l"(b), "l"(c));
    return d;
}
__device__ __forceinline__ void upk2(u64 v, float& lo, float& hi) {
    unsigned int l, h;
    asm("mov.b64 {%0, %1}, %2;" : "=r"(l), "=r"(h) : "l"(v));
    lo = __uint_as_float(l);
    hi = __uint_as_float(h);
}
#define NEG1X2 0xBF800000BF800000ULL
#define ABSMASK 0x7FFFFFFF7FFFFFFFULL

// ---------------------------------------------------------------------------
// Kernel 0: repack weights (prescaled, duplicated into f32x2 pairs), zero GAP
// ---------------------------------------------------------------------------
__global__ void pack_weights_kernel(const float* __restrict__ Wc,
                                    const float* __restrict__ We) {
    int tid = blockIdx.x * blockDim.x + threadIdx.x;   // 4096 threads
    if (tid < BB * CC) g_pooled[tid] = 0.0f;
    if (tid >= CC * CC) return;
    int c  = tid / CC;
    int oc = tid % CC;
    float2* dst = &g_wpack2[(c * CC + oc) * 10];
#pragma unroll
    for (int k = 0; k < 9; k++) {
        float w = THETA * Wc[(oc * CC + c) * 9 + k];
        dst[k] = make_float2(w, w);
    }
    float we = (1.0f - THETA) * We[oc * CC + c];
    dst[9] = make_float2(we, we);
}

// ---------------------------------------------------------------------------
// Kernel 1: fused 3x3 conv + |vertical diff| 1x1 conv + combine + partial GAP
// Block: 64 oc x (2 rows x 64 px). 256 threads. Thread: 4 oc x 2 rows x 4 px,
// computed as packed f32x2 pixel-pairs (fma.rn.f32x2 = 2 FMA/lane).
// ---------------------------------------------------------------------------
__global__ void __launch_bounds__(256, 2)
conv_kernel(const float* __restrict__ x,
            const float* __restrict__ b_conv,
            float* __restrict__ out) {
    extern __shared__ float smem[];
    float* s_in  = smem;                               // 64 ch * 4 rows * 68
    u64*   s_w   = (u64*)(smem + CC * 4 * SIN_STRIDE); // CHUNK c * 64 oc * 10 (dup pairs)
    float* s_red = (float*)(s_w + CHUNK * CC * 10);    // 64

    const int tid = threadIdx.x;
    const int x0  = blockIdx.x * TILE_X;
    const int y0  = blockIdx.y * 2;        // two output rows: y0, y0+1
    const int b   = blockIdx.z;

    // Stage input tile: rows y0-1 .. y0+2, cols x0-1 .. x0+64, all 64 ch (zero-pad)
    const float* xb = x + (size_t)b * CC * HH * WW;
    for (int idx = tid; idx < CC * 4 * 66; idx += 256) {
        int c   = idx / 264;
        int rem = idx % 264;
        int r   = rem / 66;
        int t   = rem % 66;
        int gy  = y0 - 1 + r;
        int gx  = x0 - 1 + t;
        float v = 0.0f;
        if ((unsigned)gy < HH && (unsigned)gx < WW)
            v = xb[(c * HH + gy) * WW + gx];
        s_in[(c * 4 + r) * SIN_STRIDE + t] = v;
    }
    if (tid < CC) s_red[tid] = 0.0f;

    const int px_thr = tid & 15;     // 16 px-groups of 4 px
    const int oc_thr = tid >> 4;     // 16 oc-groups of 4 oc
    const int pxbase = px_thr * 4;
    const int ocbase = oc_thr * 4;

    // acc[oc][row A/B][px-pair], packed f32x2
    u64 acc[4][2][2];
#pragma unroll
    for (int i = 0; i < 4; i++) {
        float bias = THETA * __ldg(&b_conv[ocbase + i]);
        u64 bp = pk2(bias, bias);
        acc[i][0][0] = bp; acc[i][0][1] = bp;
        acc[i][1][0] = bp; acc[i][1][1] = bp;
    }

    const float4* wsrc_all = (const float4*)g_wpack2;   // 5 float4 per (c,oc)
    float4* s_w4 = (float4*)s_w;

    for (int chunk = 0; chunk < CC / CHUNK; chunk++) {
        __syncthreads();
        // stage dup-weight chunk (coalesced float4): CHUNK*64*5 float4
        for (int idx = tid; idx < CHUNK * CC * 5; idx += 256)
            s_w4[idx] = wsrc_all[chunk * (CHUNK * CC * 5) + idx];
        __syncthreads();

#pragma unroll 1
        for (int cl = 0; cl < CHUNK; cl++) {
            const int c = chunk * CHUNK + cl;
            const float* rowp = &s_in[(c * 4) * SIN_STRIDE + pxbase];

            // Load 4 input rows, 6 floats each
            float r[4][6];
#pragma unroll
            for (int rr = 0; rr < 4; rr++) {
                float4 a = *(const float4*)(rowp + rr * SIN_STRIDE);
                float2 bq = *(const float2*)(rowp + rr * SIN_STRIDE + 4);
                r[rr][0] = a.x; r[rr][1] = a.y; r[rr][2] = a.z;
                r[rr][3] = a.w; r[rr][4] = bq.x; r[rr][5] = bq.y;
            }
            // Sliding pixel-pairs p[row][s] = (r[s], r[s+1])
            u64 p[4][5];
#pragma unroll
            for (int rr = 0; rr < 4; rr++) {
                p[rr][0] = pk2(r[rr][0], r[rr][1]);
                p[rr][1] = pk2(r[rr][1], r[rr][2]);
                p[rr][2] = pk2(r[rr][2], r[rr][3]);
                p[rr][3] = pk2(r[rr][3], r[rr][4]);
                p[rr][4] = pk2(r[rr][4], r[rr][5]);
            }
            // |vertical diff| packed: row A uses local rows 0,2; row B uses 1,3
            u64 dA0 = fma2(p[2][1], NEG1X2, p[0][1]) & ABSMASK;  // cols (1,2)
            u64 dA1 = fma2(p[2][3], NEG1X2, p[0][3]) & ABSMASK;  // cols (3,4)
            u64 dB0 = fma2(p[3][1], NEG1X2, p[1][1]) & ABSMASK;
            u64 dB1 = fma2(p[3][3], NEG1X2, p[1][3]) & ABSMASK;

#pragma unroll
            for (int i = 0; i < 4; i++) {
                const ulonglong2* wp =
                    (const ulonglong2*)&s_w[(cl * CC + ocbase + i) * 10];
                ulonglong2 w01 = wp[0];   // taps 0,1
                ulonglong2 w23 = wp[1];   // taps 2,3
                ulonglong2 w45 = wp[2];   // taps 4,5
                ulonglong2 w67 = wp[3];   // taps 6,7
                ulonglong2 w89 = wp[4];   // tap 8, edge

                // tap k = kr*3+kc : rowA operand p[kr][kc+2*jp], rowB p[kr+1][kc+2*jp]
                acc[i][0][0] = fma2(w01.x, p[0][0], acc[i][0][0]);
                acc[i][0][1] = fma2(w01.x, p[0][2], acc[i][0][1]);
                acc[i][1][0] = fma2(w01.x, p[1][0], acc[i][1][0]);
                acc[i][1][1] = fma2(w01.x, p[1][2], acc[i][1][1]);

                acc[i][0][0] = fma2(w01.y, p[0][1], acc[i][0][0]);
                acc[i][0][1] = fma2(w01.y, p[0][3], acc[i][0][1]);
                acc[i][1][0] = fma2(w01.y, p[1][1], acc[i][1][0]);
                acc[i][1][1] = fma2(w01.y, p[1][3], acc[i][1][1]);

                acc[i][0][0] = fma2(w23.x, p[0][2], acc[i][0][0]);
                acc[i][0][1] = fma2(w23.x, p[0][4], acc[i][0][1]);
                acc[i][1][0] = fma2(w23.x, p[1][2], acc[i][1][0]);
                acc[i][1][1] = fma2(w23.x, p[1][4], acc[i][1][1]);

                acc[i][0][0] = fma2(w23.y, p[1][0], acc[i][0][0]);
                acc[i][0][1] = fma2(w23.y, p[1][2], acc[i][0][1]);
                acc[i][1][0] = fma2(w23.y, p[2][0], acc[i][1][0]);
                acc[i][1][1] = fma2(w23.y, p[2][2], acc[i][1][1]);

                acc[i][0][0] = fma2(w45.x, p[1][1], acc[i][0][0]);
                acc[i][0][1] = fma2(w45.x, p[1][3], acc[i][0][1]);
                acc[i][1][0] = fma2(w45.x, p[2][1], acc[i][1][0]);
                acc[i][1][1] = fma2(w45.x, p[2][3], acc[i][1][1]);

                acc[i][0][0] = fma2(w45.y, p[1][2], acc[i][0][0]);
                acc[i][0][1] = fma2(w45.y, p[1][4], acc[i][0][1]);
                acc[i][1][0] = fma2(w45.y, p[2][2], acc[i][1][0]);
                acc[i][1][1] = fma2(w45.y, p[2][4], acc[i][1][1]);

                acc[i][0][0] = fma2(w67.x, p[2][0], acc[i][0][0]);
                acc[i][0][1] = fma2(w67.x, p[2][2], acc[i][0][1]);
                acc[i][1][0] = fma2(w67.x, p[3][0], acc[i][1][0]);
                acc[i][1][1] = fma2(w67.x, p[3][2], acc[i][1][1]);

                acc[i][0][0] = fma2(w67.y, p[2][1], acc[i][0][0]);
                acc[i][0][1] = fma2(w67.y, p[2][3], acc[i][0][1]);
                acc[i][1][0] = fma2(w67.y, p[3][1], acc[i][1][0]);
                acc[i][1][1] = fma2(w67.y, p[3][3], acc[i][1][1]);

                acc[i][0][0] = fma2(w89.x, p[2][2], acc[i][0][0]);
                acc[i][0][1] = fma2(w89.x, p[2][4], acc[i][0][1]);
                acc[i][1][0] = fma2(w89.x, p[3][2], acc[i][1][0]);
                acc[i][1][1] = fma2(w89.x, p[3][4], acc[i][1][1]);

                acc[i][0][0] = fma2(w89.y, dA0, acc[i][0][0]);
                acc[i][0][1] = fma2(w89.y, dA1, acc[i][0][1]);
                acc[i][1][0] = fma2(w89.y, dB0, acc[i][1][0]);
                acc[i][1][1] = fma2(w89.y, dB1, acc[i][1][1]);
            }
        }
    }

    // Unpack, store (float4 coalesced), and accumulate GAP partials
#pragma unroll
    for (int i = 0; i < 4; i++) {
        const int oc = ocbase + i;
        float sum = 0.0f;
#pragma unroll
        for (int rsel = 0; rsel < 2; rsel++) {
            float4 v;
            upk2(acc[i][rsel][0], v.x, v.y);
            upk2(acc[i][rsel][1], v.z, v.w);
            *(float4*)&out[(((size_t)b * CC + oc) * HH + (y0 + rsel)) * WW + x0 + pxbase] = v;
            sum += v.x + v.y + v.z + v.w;
        }
        atomicAdd(&s_red[oc], sum);
    }
    __syncthreads();
    if (tid < CC) atomicAdd(&g_pooled[b * CC + tid], s_red[tid]);
}

// ---------------------------------------------------------------------------
// Kernel 2: SE attention (GAP -> 1x1 -> ReLU -> 1x1 -> sigmoid), 1 block
// ---------------------------------------------------------------------------
__global__ void attn_kernel(const float* __restrict__ W1, const float* __restrict__ b1,
                            const float* __restrict__ W2, const float* __restrict__ b2) {
    __shared__ float sh[BB * 8];
    const int t = threadIdx.x;
    if (t < BB * 8) {
        int b = t >> 3, r = t & 7;
        float s = b1[r];
        const float inv = 1.0f / (float)(HH * WW);
#pragma unroll
        for (int c = 0; c < CC; c++)
            s += (g_pooled[b * CC + c] * inv) * W1[r * CC + c];
        sh[t] = fmaxf(s, 0.0f);
    }
    __syncthreads();
    for (int idx = t; idx < BB * CC; idx += 256) {
        int b = idx >> 6, o = idx & 63;
        float s = b2[o];
#pragma unroll
        for (int r = 0; r < 8; r++)
            s += sh[b * 8 + r] * W2[o * 8 + r];
        g_attn[idx] = 1.0f / (1.0f + expf(-s));
    }
}

// ---------------------------------------------------------------------------
// Kernel 3: scale output by per-(b,c) attention (float4 grid)
// ---------------------------------------------------------------------------
__global__ void scale_kernel(float* __restrict__ out) {
    int i = blockIdx.x * blockDim.x + threadIdx.x;   // exactly B*C*H*W/4 threads
    float4 v = ((float4*)out)[i];
    float a = g_attn[i >> 14];                       // 65536/4 float4 per (b,c)
    v.x *= a; v.y *= a; v.z *= a; v.w *= a;
    ((float4*)out)[i] = v;
}

// ---------------------------------------------------------------------------
extern "C" void kernel_launch(void* const* d_in, const int* in_sizes, int n_in,
                              void* d_out, int out_size) {
    const float* x  = (const float*)d_in[0];
    const float* Wc = (const float*)d_in[1];
    const float* bc = (const float*)d_in[2];
    const float* We = (const float*)d_in[3];
    const float* W1 = (const float*)d_in[4];
    const float* b1 = (const float*)d_in[5];
    const float* W2 = (const float*)d_in[6];
    const float* b2 = (const float*)d_in[7];
    float* out = (float*)d_out;

    // 69632 (input) + 40960 (dup weights) + 256 (reduction) = 110848 bytes
    const int smem_bytes = CC * 4 * SIN_STRIDE * 4 + CHUNK * CC * 10 * 8 + CC * 4;
    cudaFuncSetAttribute(conv_kernel, cudaFuncAttributeMaxDynamicSharedMemorySize, smem_bytes);

    pack_weights_kernel<<<16, 256>>>(Wc, We);

    dim3 grid(WW / TILE_X, HH / 2, BB);
    conv_kernel<<<grid, 256, smem_bytes>>>(x, bc, out);

    attn_kernel<<<1, 256>>>(W1, b1, W2, b2);

    scale_kernel<<<(BB * CC * HH * WW / 4) / 256, 256>>>(out);
}

// round 9
// speedup vs baseline: 1.3541x; 1.3500x over previous
#include <cuda_runtime.h>
#include <cuda_bf16.h>
#include <math.h>
#include <stdint.h>

#define BB 8
#define CC 64
#define HH 256
#define WW 256
#define THETA 0.7f

#define NCOL 130             // staged cols: x0-1 .. x0+128
#define CPAD 72              // padded channel entries -> 144B rows (16B aligned, conflict-free ldmatrix)
#define RAW_PLANE_B (4 * NCOL * CPAD * 2)       // 74880 (rows 0..2 input, row 3 = edge)
#define B_OFF       (2 * RAW_PLANE_B)           // 149760
#define B_PLANE_B   (64 * CPAD * 2)             // 9216
#define B_TAP_B     (2 * B_PLANE_B)             // 18432
#define SMEM_BYTES  (B_OFF + 2 * B_TAP_B)       // 186624

__device__ float g_pooled[BB * CC];
__device__ float g_attn[BB * CC];
__device__ uint4 g_B[10 * B_TAP_B / 16];        // [tap][plane][64 oc][72 c] bf16, zero-init pad

// ---------------- helpers ----------------
__device__ __forceinline__ uint32_t smem_u32(const void* p) {
    uint32_t a;
    asm("{ .reg .u64 t; cvta.to.shared.u64 t, %1; cvt.u32.u64 %0, t; }" : "=r"(a) : "l"(p));
    return a;
}
#define LDM4(r0, r1, r2, r3, a) \
    asm volatile("ldmatrix.sync.aligned.m8n8.x4.shared.b16 {%0,%1,%2,%3}, [%4];" \
                 : "=r"(r0), "=r"(r1), "=r"(r2), "=r"(r3) : "r"(a))
#define LDM2(r0, r1, a) \
    asm volatile("ldmatrix.sync.aligned.m8n8.x2.shared.b16 {%0,%1}, [%2];" \
                 : "=r"(r0), "=r"(r1) : "r"(a))
#define MMA(c, a, b) \
    asm volatile("mma.sync.aligned.m16n8k16.row.col.f32.bf16.bf16.f32 " \
                 "{%0,%1,%2,%3},{%4,%5,%6,%7},{%8,%9},{%0,%1,%2,%3};" \
                 : "+f"((c)[0]), "+f"((c)[1]), "+f"((c)[2]), "+f"((c)[3]) \
                 : "r"((a)[0]), "r"((a)[1]), "r"((a)[2]), "r"((a)[3]), \
                   "r"((b)[0]), "r"((b)[1]))
#define CP16(s, g) \
    asm volatile("cp.async.cg.shared.global [%0], [%1], 16;" :: "r"(s), "l"(g))
#define CP_COMMIT() asm volatile("cp.async.commit_group;")

__device__ __forceinline__ void split2(float v, unsigned short& h, unsigned short& l) {
    __nv_bfloat16 hb = __float2bfloat16(v);
    __nv_bfloat16 lb = __float2bfloat16(v - __bfloat162float(hb));
    h = __bfloat16_as_ushort(hb);
    l = __bfloat16_as_ushort(lb);
}
__device__ __forceinline__ float join2(unsigned short h, unsigned short l) {
    return __bfloat162float(__ushort_as_bfloat16(h)) + __bfloat162float(__ushort_as_bfloat16(l));
}

// ---------------------------------------------------------------------------
// Kernel 0: prepack prescaled bf16 hi/lo weight planes; zero GAP accumulator.
// tap t<9: w = THETA * Wc[oc][c][t/3][t%3];  t==9: w = (1-THETA) * We[oc][c]
// ---------------------------------------------------------------------------
__global__ void prepack_kernel(const float* __restrict__ Wc,
                               const float* __restrict__ We) {
    int idx = blockIdx.x * blockDim.x + threadIdx.x;   // 40960 threads
    if (idx < BB * CC) g_pooled[idx] = 0.0f;
    if (idx >= 10 * CC * CC) return;
    int t  = idx >> 12;
    int oc = (idx >> 6) & 63;
    int c  = idx & 63;
    float w = (t < 9) ? THETA * Wc[((oc * CC + c) * 3 + t / 3) * 3 + (t % 3)]
                      : (1.0f - THETA) * We[oc * CC + c];
    unsigned short h, l;
    split2(w, h, l);
    unsigned short* gb = (unsigned short*)g_B;
    gb[(t * 2 + 0) * (64 * CPAD) + oc * CPAD + c] = h;
    gb[(t * 2 + 1) * (64 * CPAD) + oc * CPAD + c] = l;
}

// ---------------------------------------------------------------------------
// Kernel 1: HMMA implicit-GEMM conv. Grid (2, 256, 8), 256 threads (8 warps).
// Warp w: px slice 32*(w&3), oc slice 32*(w>>2). Acc: fp32 regs, 2m x 4n x 4.
// ---------------------------------------------------------------------------
__global__ void __launch_bounds__(256, 1)
conv_kernel(const float* __restrict__ x,
            const float* __restrict__ b_conv,
            float* __restrict__ out) {
    extern __shared__ __align__(16) unsigned char smem[];
    __shared__ float s_red[CC];

    unsigned short* rawH = (unsigned short*)smem;
    unsigned short* rawL = (unsigned short*)(smem + RAW_PLANE_B);
    const uint32_t sbase = smem_u32(smem);
    const uint32_t sB_a  = sbase + B_OFF;

    const int tid  = threadIdx.x;
    const int lane = tid & 31;
    const int wid  = tid >> 5;
    const int x0   = blockIdx.x * 128;
    const int y    = blockIdx.y;
    const int b    = blockIdx.z;

    if (tid < CC) s_red[tid] = 0.0f;

    // ---- stage input rows y-1..y+1 as bf16 hi/lo planes, layout [r][col][c]
    const float* xb = x + (size_t)b * CC * HH * WW;
    for (int idx = tid; idx < CC * 3 * NCOL; idx += 256) {
        int c   = idx / (3 * NCOL);
        int rem = idx % (3 * NCOL);
        int r   = rem / NCOL;
        int col = rem % NCOL;
        int gy  = y - 1 + r;
        int gx  = x0 - 1 + col;
        float v = 0.0f;
        if ((unsigned)gy < HH && (unsigned)gx < WW)
            v = xb[(c * HH + gy) * WW + gx];
        unsigned short h, l;
        split2(v, h, l);
        int o = (r * NCOL + col) * CPAD + c;
        rawH[o] = h;
        rawL[o] = l;
    }
    __syncthreads();

    // ---- build edge row (row 3): |x(y-1) - x(y+1)| ; c-fast -> conflict-free
    for (int idx = tid; idx < NCOL * CC; idx += 256) {
        int col = idx >> 6;
        int c   = idx & 63;
        int o0 = (0 * NCOL + col) * CPAD + c;
        int o2 = (2 * NCOL + col) * CPAD + c;
        float e = fabsf(join2(rawH[o0], rawL[o0]) - join2(rawH[o2], rawL[o2]));
        unsigned short h, l;
        split2(e, h, l);
        int o3 = (3 * NCOL + col) * CPAD + c;
        rawH[o3] = h;
        rawL[o3] = l;
    }

    // ---- prefetch B tap 0 (both planes) via cp.async
    const char* gB = (const char*)g_B;
    for (int i = tid; i < B_TAP_B / 16; i += 256)
        CP16(sB_a + i * 16, gB + i * 16);
    CP_COMMIT();
    __syncthreads();   // edge row visible before compute

    float acc[2][4][4];
#pragma unroll
    for (int mi = 0; mi < 2; mi++)
#pragma unroll
        for (int ni = 0; ni < 4; ni++)
#pragma unroll
            for (int r = 0; r < 4; r++) acc[mi][ni][r] = 0.0f;

    const int px0 = (wid & 3) * 32;
    const int oc0 = (wid >> 2) * 32;
    const int arow_lane = lane & 15;            // px offset within 16-row frag
    const int acol_lane = (lane >> 4) * 8;      // c offset (mats 2,3)
    const int boc_lane  = lane & 7;             // oc row within 8
    const int bk_lane   = ((lane >> 3) & 1) * 8;

#pragma unroll 1
    for (int t = 0; t < 10; t++) {
        const int buf = t & 1;
        if (t < 9) {   // prefetch tap t+1 into the other buffer
            const char* src = gB + (t + 1) * B_TAP_B;
            uint32_t dst = sB_a + ((t + 1) & 1) * B_TAP_B;
            for (int i = tid; i < B_TAP_B / 16; i += 256)
                CP16(dst + i * 16, src + i * 16);
            CP_COMMIT();
            asm volatile("cp.async.wait_group 1;" ::: "memory");
        } else {
            asm volatile("cp.async.wait_group 0;" ::: "memory");
        }
        __syncthreads();   // B buffer visible to all warps

        const int dy = (t < 9) ? t / 3 : 3;
        const int dx = (t < 9) ? t % 3 : 1;

        // A fragments (hi & lo) straight from raw planes via ldmatrix.x4
        uint32_t Ah[2][4][4], Al[2][4][4];
        const int rbase = (dy * NCOL + px0 + dx + arow_lane) * CPAD + acol_lane;
#pragma unroll
        for (int mi = 0; mi < 2; mi++) {
#pragma unroll
            for (int ki = 0; ki < 4; ki++) {
                int o = rbase + mi * 16 * CPAD + ki * 16;
                LDM4(Ah[mi][ki][0], Ah[mi][ki][1], Ah[mi][ki][2], Ah[mi][ki][3],
                     sbase + (uint32_t)(o * 2));
                LDM4(Al[mi][ki][0], Al[mi][ki][1], Al[mi][ki][2], Al[mi][ki][3],
                     sbase + RAW_PLANE_B + (uint32_t)(o * 2));
            }
        }

        const uint32_t bufH = sB_a + buf * B_TAP_B;
        const uint32_t bufL = bufH + B_PLANE_B;
#pragma unroll
        for (int ni = 0; ni < 4; ni++) {
            uint32_t Bh[4][2], Bl[4][2];
#pragma unroll
            for (int ki = 0; ki < 4; ki++) {
                int bo = ((oc0 + ni * 8 + boc_lane) * CPAD + ki * 16 + bk_lane) * 2;
                LDM2(Bh[ki][0], Bh[ki][1], bufH + (uint32_t)bo);
                LDM2(Bl[ki][0], Bl[ki][1], bufL + (uint32_t)bo);
            }
#pragma unroll
            for (int mi = 0; mi < 2; mi++)
#pragma unroll
                for (int ki = 0; ki < 4; ki++) MMA(acc[mi][ni], Ah[mi][ki], Bh[ki]);
#pragma unroll
            for (int mi = 0; mi < 2; mi++)
#pragma unroll
                for (int ki = 0; ki < 4; ki++) MMA(acc[mi][ni], Ah[mi][ki], Bl[ki]);
#pragma unroll
            for (int mi = 0; mi < 2; mi++)
#pragma unroll
                for (int ki = 0; ki < 4; ki++) MMA(acc[mi][ni], Al[mi][ki], Bh[ki]);
        }
        __syncthreads();   // all warps done with buf before it is re-staged
    }

    // ---- epilogue: bias, store, GAP
#pragma unroll
    for (int ni = 0; ni < 4; ni++) {
        const int oca = oc0 + ni * 8 + 2 * (lane & 3);
        const float ba = THETA * __ldg(&b_conv[oca]);
        const float bb = THETA * __ldg(&b_conv[oca + 1]);
        float sA = 0.0f, sB = 0.0f;
#pragma unroll
        for (int mi = 0; mi < 2; mi++) {
            float d0 = acc[mi][ni][0] + ba;
            float d1 = acc[mi][ni][1] + bb;
            float d2 = acc[mi][ni][2] + ba;
            float d3 = acc[mi][ni][3] + bb;
            int pxg = x0 + px0 + mi * 16 + (lane >> 2);
            size_t base = ((size_t)b * CC + oca) * (size_t)(HH * WW) + (size_t)y * WW + pxg;
            out[base]               = d0;
            out[base + HH * WW]     = d1;
            out[base + 8]           = d2;
            out[base + HH * WW + 8] = d3;
            sA += d0 + d2;
            sB += d1 + d3;
        }
#pragma unroll
        for (int s = 4; s < 32; s <<= 1) {
            sA += __shfl_xor_sync(0xffffffffu, sA, s);
            sB += __shfl_xor_sync(0xffffffffu, sB, s);
        }
        if (lane < 4) {
            atomicAdd(&s_red[oca], sA);
            atomicAdd(&s_red[oca + 1], sB);
        }
    }
    __syncthreads();
    if (tid < CC) atomicAdd(&g_pooled[b * CC + tid], s_red[tid]);
}

// ---------------------------------------------------------------------------
// Kernel 2: SE attention (GAP -> 1x1 -> ReLU -> 1x1 -> sigmoid), 1 block
// ---------------------------------------------------------------------------
__global__ void attn_kernel(const float* __restrict__ W1, const float* __restrict__ b1,
                            const float* __restrict__ W2, const float* __restrict__ b2) {
    __shared__ float sh[BB * 8];
    const int t = threadIdx.x;
    if (t < BB * 8) {
        int b = t >> 3, r = t & 7;
        float s = b1[r];
        const float inv = 1.0f / (float)(HH * WW);
#pragma unroll
        for (int c = 0; c < CC; c++)
            s += (g_pooled[b * CC + c] * inv) * W1[r * CC + c];
        sh[t] = fmaxf(s, 0.0f);
    }
    __syncthreads();
    for (int idx = t; idx < BB * CC; idx += 256) {
        int b = idx >> 6, o = idx & 63;
        float s = b2[o];
#pragma unroll
        for (int r = 0; r < 8; r++)
            s += sh[b * 8 + r] * W2[o * 8 + r];
        g_attn[idx] = 1.0f / (1.0f + expf(-s));
    }
}

// ---------------------------------------------------------------------------
// Kernel 3: scale output by per-(b,c) attention (float4 grid)
// ---------------------------------------------------------------------------
__global__ void scale_kernel(float* __restrict__ out) {
    int i = blockIdx.x * blockDim.x + threadIdx.x;
    float4 v = ((float4*)out)[i];
    float a = g_attn[i >> 14];           // 16384 float4 per (b,c)
    v.x *= a; v.y *= a; v.z *= a; v.w *= a;
    ((float4*)out)[i] = v;
}

// ---------------------------------------------------------------------------
extern "C" void kernel_launch(void* const* d_in, const int* in_sizes, int n_in,
                              void* d_out, int out_size) {
    const float* x  = (const float*)d_in[0];
    const float* Wc = (const float*)d_in[1];
    const float* bc = (const float*)d_in[2];
    const float* We = (const float*)d_in[3];
    const float* W1 = (const float*)d_in[4];
    const float* b1 = (const float*)d_in[5];
    const float* W2 = (const float*)d_in[6];
    const float* b2 = (const float*)d_in[7];
    float* out = (float*)d_out;

    cudaFuncSetAttribute(conv_kernel, cudaFuncAttributeMaxDynamicSharedMemorySize, SMEM_BYTES);

    prepack_kernel<<<160, 256>>>(Wc, We);

    dim3 grid(WW / 128, HH, BB);
    conv_kernel<<<grid, 256, SMEM_BYTES>>>(x, bc, out);

    attn_kernel<<<1, 256>>>(W1, b1, W2, b2);

    scale_kernel<<<(BB * CC * HH * WW / 4) / 256, 256>>>(out);
}

// round 10
// speedup vs baseline: 1.8661x; 1.3780x over previous
#include <cuda_runtime.h>
#include <cuda_bf16.h>
#include <math.h>
#include <stdint.h>

#define BB 8
#define CC 64
#define HH 256
#define WW 256
#define THETA 0.7f

#define PX   64              // pixels per CTA
#define NCOL 66              // staged cols: x0-1 .. x0+64
#define CPAD 72              // padded channels -> 144B rows (conflict-free ldmatrix)
#define RAW_PLANE_B (4 * NCOL * CPAD * 2)       // 38016 (rows 0..2 input, row 3 = edge)
#define B_OFF       (2 * RAW_PLANE_B)           // 76032
#define B_PLANE_B   (64 * CPAD * 2)             // 9216
#define B_TAP_B     (2 * B_PLANE_B)             // 18432
#define SMEM_BYTES  (B_OFF + 2 * B_TAP_B)       // 112896 -> 2 CTAs/SM

__device__ float g_pooled[BB * CC];
__device__ float g_attn[BB * CC];
__device__ uint4 g_B[10 * B_TAP_B / 16];        // [tap][plane][64 oc][72 c] bf16

// ---------------- helpers ----------------
__device__ __forceinline__ uint32_t smem_u32(const void* p) {
    uint32_t a;
    asm("{ .reg .u64 t; cvta.to.shared.u64 t, %1; cvt.u32.u64 %0, t; }" : "=r"(a) : "l"(p));
    return a;
}
#define LDM4(r0, r1, r2, r3, a) \
    asm volatile("ldmatrix.sync.aligned.m8n8.x4.shared.b16 {%0,%1,%2,%3}, [%4];" \
                 : "=r"(r0), "=r"(r1), "=r"(r2), "=r"(r3) : "r"(a))
#define LDM2(r0, r1, a) \
    asm volatile("ldmatrix.sync.aligned.m8n8.x2.shared.b16 {%0,%1}, [%2];" \
                 : "=r"(r0), "=r"(r1) : "r"(a))
#define MMA(c, a, b) \
    asm volatile("mma.sync.aligned.m16n8k16.row.col.f32.bf16.bf16.f32 " \
                 "{%0,%1,%2,%3},{%4,%5,%6,%7},{%8,%9},{%0,%1,%2,%3};" \
                 : "+f"((c)[0]), "+f"((c)[1]), "+f"((c)[2]), "+f"((c)[3]) \
                 : "r"((a)[0]), "r"((a)[1]), "r"((a)[2]), "r"((a)[3]), \
                   "r"((b)[0]), "r"((b)[1]))
#define CP16(s, g) \
    asm volatile("cp.async.cg.shared.global [%0], [%1], 16;" :: "r"(s), "l"(g))
#define CP_COMMIT()  asm volatile("cp.async.commit_group;")
#define CP_WAIT0()   asm volatile("cp.async.wait_group 0;" ::: "memory")

__device__ __forceinline__ void split2(float v, unsigned short& h, unsigned short& l) {
    __nv_bfloat16 hb = __float2bfloat16(v);
    __nv_bfloat16 lb = __float2bfloat16(v - __bfloat162float(hb));
    h = __bfloat16_as_ushort(hb);
    l = __bfloat16_as_ushort(lb);
}
__device__ __forceinline__ float join2(unsigned short h, unsigned short l) {
    return __bfloat162float(__ushort_as_bfloat16(h)) + __bfloat162float(__ushort_as_bfloat16(l));
}

// ---------------------------------------------------------------------------
// Kernel 0: prepack prescaled bf16 hi/lo weight planes; zero GAP accumulator.
// tap t<9: w = THETA * Wc[oc][c][t/3][t%3];  t==9: w = (1-THETA) * We[oc][c]
// ---------------------------------------------------------------------------
__global__ void prepack_kernel(const float* __restrict__ Wc,
                               const float* __restrict__ We) {
    int idx = blockIdx.x * blockDim.x + threadIdx.x;
    if (idx < BB * CC) g_pooled[idx] = 0.0f;
    if (idx >= 10 * CC * CC) return;
    int t  = idx >> 12;
    int oc = (idx >> 6) & 63;
    int c  = idx & 63;
    float w = (t < 9) ? THETA * Wc[((oc * CC + c) * 3 + t / 3) * 3 + (t % 3)]
                      : (1.0f - THETA) * We[oc * CC + c];
    unsigned short h, l;
    split2(w, h, l);
    unsigned short* gb = (unsigned short*)g_B;
    gb[(t * 2 + 0) * (64 * CPAD) + oc * CPAD + c] = h;
    gb[(t * 2 + 1) * (64 * CPAD) + oc * CPAD + c] = l;
}

// ---------------------------------------------------------------------------
// Kernel 1: HMMA implicit-GEMM conv. Grid (4, 256, 8), 256 threads, 2 CTA/SM.
// Warp w: px slice 16*(w&3), oc slice 32*(w>>2). Acc: fp32 regs, 4n x 4.
// ---------------------------------------------------------------------------
__global__ void __launch_bounds__(256, 2)
conv_kernel(const float* __restrict__ x,
            const float* __restrict__ b_conv,
            float* __restrict__ out) {
    extern __shared__ __align__(16) unsigned char smem[];
    __shared__ float s_red[CC];

    unsigned short* rawH = (unsigned short*)smem;
    unsigned short* rawL = (unsigned short*)(smem + RAW_PLANE_B);
    const uint32_t sbase = smem_u32(smem);
    const uint32_t sB_a  = sbase + B_OFF;

    const int tid  = threadIdx.x;
    const int lane = tid & 31;
    const int wid  = tid >> 5;
    const int x0   = blockIdx.x * PX;
    const int y    = blockIdx.y;
    const int b    = blockIdx.z;

    if (tid < CC) s_red[tid] = 0.0f;

    // ---- stage input rows y-1..y+1 as bf16 hi/lo planes, layout [r][col][c]
    const float* xb = x + (size_t)b * CC * HH * WW;
    for (int idx = tid; idx < CC * 3 * NCOL; idx += 256) {
        int c   = idx / (3 * NCOL);
        int rem = idx % (3 * NCOL);
        int r   = rem / NCOL;
        int col = rem % NCOL;
        int gy  = y - 1 + r;
        int gx  = x0 - 1 + col;
        float v = 0.0f;
        if ((unsigned)gy < HH && (unsigned)gx < WW)
            v = xb[(c * HH + gy) * WW + gx];
        unsigned short h, l;
        split2(v, h, l);
        int o = (r * NCOL + col) * CPAD + c;
        rawH[o] = h;
        rawL[o] = l;
    }
    __syncthreads();

    // ---- edge row (row 3): |x(y-1) - x(y+1)|
    for (int idx = tid; idx < NCOL * CC; idx += 256) {
        int col = idx >> 6;
        int c   = idx & 63;
        int o0 = (0 * NCOL + col) * CPAD + c;
        int o2 = (2 * NCOL + col) * CPAD + c;
        float e = fabsf(join2(rawH[o0], rawL[o0]) - join2(rawH[o2], rawL[o2]));
        unsigned short h, l;
        split2(e, h, l);
        int o3 = (3 * NCOL + col) * CPAD + c;
        rawH[o3] = h;
        rawL[o3] = l;
    }

    // ---- prefetch B tap 0
    const char* gB = (const char*)g_B;
    for (int i = tid; i < B_TAP_B / 16; i += 256)
        CP16(sB_a + i * 16, gB + i * 16);
    CP_COMMIT();

    float acc[4][4];
#pragma unroll
    for (int ni = 0; ni < 4; ni++)
#pragma unroll
        for (int r = 0; r < 4; r++) acc[ni][r] = 0.0f;

    const int px0 = (wid & 3) * 16;
    const int oc0 = (wid >> 2) * 32;
    const int arow_lane = lane & 15;
    const int acol_lane = (lane >> 4) * 8;
    const int boc_lane  = lane & 7;
    const int bk_lane   = ((lane >> 3) & 1) * 8;

#pragma unroll 1
    for (int t = 0; t < 10; t++) {
        const int buf = t & 1;
        CP_WAIT0();        // tap t's B copy complete (this thread's part)
        __syncthreads();   // all threads' parts visible; buf^1 free; edge row visible (t=0)

        if (t < 9) {       // prefetch tap t+1 into the other buffer (overlaps compute)
            const char* src = gB + (t + 1) * B_TAP_B;
            uint32_t dst = sB_a + ((t + 1) & 1) * B_TAP_B;
            for (int i = tid; i < B_TAP_B / 16; i += 256)
                CP16(dst + i * 16, src + i * 16);
            CP_COMMIT();
        }

        const int dy = (t < 9) ? t / 3 : 3;
        const int dx = (t < 9) ? t % 3 : 1;

        // A fragments (hi & lo) straight from raw planes via ldmatrix.x4
        uint32_t Ah[4][4], Al[4][4];
        const int rbase = (dy * NCOL + px0 + dx + arow_lane) * CPAD + acol_lane;
#pragma unroll
        for (int ki = 0; ki < 4; ki++) {
            int o = rbase + ki * 16;
            LDM4(Ah[ki][0], Ah[ki][1], Ah[ki][2], Ah[ki][3],
                 sbase + (uint32_t)(o * 2));
            LDM4(Al[ki][0], Al[ki][1], Al[ki][2], Al[ki][3],
                 sbase + RAW_PLANE_B + (uint32_t)(o * 2));
        }

        const uint32_t bufH = sB_a + buf * B_TAP_B;
        const uint32_t bufL = bufH + B_PLANE_B;
#pragma unroll
        for (int ni = 0; ni < 4; ni++) {
            uint32_t Bh[4][2], Bl[4][2];
#pragma unroll
            for (int ki = 0; ki < 4; ki++) {
                int bo = ((oc0 + ni * 8 + boc_lane) * CPAD + ki * 16 + bk_lane) * 2;
                LDM2(Bh[ki][0], Bh[ki][1], bufH + (uint32_t)bo);
                LDM2(Bl[ki][0], Bl[ki][1], bufL + (uint32_t)bo);
            }
#pragma unroll
            for (int ki = 0; ki < 4; ki++) MMA(acc[ni], Ah[ki], Bh[ki]);
#pragma unroll
            for (int ki = 0; ki < 4; ki++) MMA(acc[ni], Ah[ki], Bl[ki]);
#pragma unroll
            for (int ki = 0; ki < 4; ki++) MMA(acc[ni], Al[ki], Bh[ki]);
        }
    }

    // ---- epilogue: bias, store, GAP
#pragma unroll
    for (int ni = 0; ni < 4; ni++) {
        const int oca = oc0 + ni * 8 + 2 * (lane & 3);
        const float ba = THETA * __ldg(&b_conv[oca]);
        const float bb = THETA * __ldg(&b_conv[oca + 1]);
        float d0 = acc[ni][0] + ba;
        float d1 = acc[ni][1] + bb;
        float d2 = acc[ni][2] + ba;
        float d3 = acc[ni][3] + bb;
        int pxg = x0 + px0 + (lane >> 2);
        size_t base = ((size_t)b * CC + oca) * (size_t)(HH * WW) + (size_t)y * WW + pxg;
        out[base]               = d0;
        out[base + HH * WW]     = d1;
        out[base + 8]           = d2;
        out[base + HH * WW + 8] = d3;
        float sA = d0 + d2;
        float sB = d1 + d3;
#pragma unroll
        for (int s = 4; s < 32; s <<= 1) {
            sA += __shfl_xor_sync(0xffffffffu, sA, s);
            sB += __shfl_xor_sync(0xffffffffu, sB, s);
        }
        if (lane < 4) {
            atomicAdd(&s_red[oca], sA);
            atomicAdd(&s_red[oca + 1], sB);
        }
    }
    __syncthreads();
    if (tid < CC) atomicAdd(&g_pooled[b * CC + tid], s_red[tid]);
}

// ---------------------------------------------------------------------------
// Kernel 2: SE attention (GAP -> 1x1 -> ReLU -> 1x1 -> sigmoid), 1 block
// ---------------------------------------------------------------------------
__global__ void attn_kernel(const float* __restrict__ W1, const float* __restrict__ b1,
                            const float* __restrict__ W2, const float* __restrict__ b2) {
    __shared__ float sh[BB * 8];
    const int t = threadIdx.x;
    if (t < BB * 8) {
        int b = t >> 3, r = t & 7;
        float s = b1[r];
        const float inv = 1.0f / (float)(HH * WW);
#pragma unroll
        for (int c = 0; c < CC; c++)
            s += (g_pooled[b * CC + c] * inv) * W1[r * CC + c];
        sh[t] = fmaxf(s, 0.0f);
    }
    __syncthreads();
    for (int idx = t; idx < BB * CC; idx += 256) {
        int b = idx >> 6, o = idx & 63;
        float s = b2[o];
#pragma unroll
        for (int r = 0; r < 8; r++)
            s += sh[b * 8 + r] * W2[o * 8 + r];
        g_attn[idx] = 1.0f / (1.0f + expf(-s));
    }
}

// ---------------------------------------------------------------------------
// Kernel 3: scale output by per-(b,c) attention (float4 grid)
// ---------------------------------------------------------------------------
__global__ void scale_kernel(float* __restrict__ out) {
    int i = blockIdx.x * blockDim.x + threadIdx.x;
    float4 v = ((float4*)out)[i];
    float a = g_attn[i >> 14];           // 16384 float4 per (b,c)
    v.x *= a; v.y *= a; v.z *= a; v.w *= a;
    ((float4*)out)[i] = v;
}

// ---------------------------------------------------------------------------
extern "C" void kernel_launch(void* const* d_in, const int* in_sizes, int n_in,
                              void* d_out, int out_size) {
    const float* x  = (const float*)d_in[0];
    const float* Wc = (const float*)d_in[1];
    const float* bc = (const float*)d_in[2];
    const float* We = (const float*)d_in[3];
    const float* W1 = (const float*)d_in[4];
    const float* b1 = (const float*)d_in[5];
    const float* W2 = (const float*)d_in[6];
    const float* b2 = (const float*)d_in[7];
    float* out = (float*)d_out;

    cudaFuncSetAttribute(conv_kernel, cudaFuncAttributeMaxDynamicSharedMemorySize, SMEM_BYTES);

    prepack_kernel<<<160, 256>>>(Wc, We);

    dim3 grid(WW / PX, HH, BB);
    conv_kernel<<<grid, 256, SMEM_BYTES>>>(x, bc, out);

    attn_kernel<<<1, 256>>>(W1, b1, W2, b2);

    scale_kernel<<<(BB * CC * HH * WW / 4) / 256, 256>>>(out);
}

// round 11
// speedup vs baseline: 1.8749x; 1.0048x over previous
#include <cuda_runtime.h>
#include <cuda_bf16.h>
#include <math.h>
#include <stdint.h>

#define BB 8
#define CC 64
#define HH 256
#define WW 256
#define THETA 0.7f

#define PX   64              // pixels per CTA
#define NCOL 66              // staged cols: x0-1 .. x0+64
#define CPAD 72              // padded channels -> 144B rows (conflict-free ldmatrix)
#define RAW_PLANE_B (4 * NCOL * CPAD * 2)       // 38016 (rows 0..2 input, row 3 = edge)
#define B_OFF       (2 * RAW_PLANE_B)           // 76032
#define B_PLANE_B   (64 * CPAD * 2)             // 9216
#define B_TAP_B     (2 * B_PLANE_B)             // 18432
#define SMEM_BYTES  (B_OFF + 2 * B_TAP_B)       // 112896 -> 2 CTAs/SM

__device__ float g_pooled[BB * CC];
__device__ float g_attn[BB * CC];
__device__ uint4 g_B[10 * B_TAP_B / 16];        // [tap][plane][64 oc][72 c] bf16

// ---------------- helpers ----------------
__device__ __forceinline__ uint32_t smem_u32(const void* p) {
    uint32_t a;
    asm("{ .reg .u64 t; cvta.to.shared.u64 t, %1; cvt.u32.u64 %0, t; }" : "=r"(a) : "l"(p));
    return a;
}
#define LDM4(r0, r1, r2, r3, a) \
    asm volatile("ldmatrix.sync.aligned.m8n8.x4.shared.b16 {%0,%1,%2,%3}, [%4];" \
                 : "=r"(r0), "=r"(r1), "=r"(r2), "=r"(r3) : "r"(a))
#define MMA(c, a, b) \
    asm volatile("mma.sync.aligned.m16n8k16.row.col.f32.bf16.bf16.f32 " \
                 "{%0,%1,%2,%3},{%4,%5,%6,%7},{%8,%9},{%0,%1,%2,%3};" \
                 : "+f"((c)[0]), "+f"((c)[1]), "+f"((c)[2]), "+f"((c)[3]) \
                 : "r"((a)[0]), "r"((a)[1]), "r"((a)[2]), "r"((a)[3]), \
                   "r"((b)[0]), "r"((b)[1]))
#define CP16(s, g) \
    asm volatile("cp.async.cg.shared.global [%0], [%1], 16;" :: "r"(s), "l"(g))
#define CP_COMMIT()  asm volatile("cp.async.commit_group;")
#define CP_WAIT0()   asm volatile("cp.async.wait_group 0;" ::: "memory")

__device__ __forceinline__ void split2(float v, unsigned short& h, unsigned short& l) {
    __nv_bfloat16 hb = __float2bfloat16(v);
    __nv_bfloat16 lb = __float2bfloat16(v - __bfloat162float(hb));
    h = __bfloat16_as_ushort(hb);
    l = __bfloat16_as_ushort(lb);
}
__device__ __forceinline__ float join2(unsigned short h, unsigned short l) {
    return __bfloat162float(__ushort_as_bfloat16(h)) + __bfloat162float(__ushort_as_bfloat16(l));
}

// ---------------------------------------------------------------------------
// Kernel 0: prepack prescaled bf16 hi/lo weight planes; zero GAP accumulator.
// ---------------------------------------------------------------------------
__global__ void prepack_kernel(const float* __restrict__ Wc,
                               const float* __restrict__ We) {
    int idx = blockIdx.x * blockDim.x + threadIdx.x;
    if (idx < BB * CC) g_pooled[idx] = 0.0f;
    if (idx >= 10 * CC * CC) return;
    int t  = idx >> 12;
    int oc = (idx >> 6) & 63;
    int c  = idx & 63;
    float w = (t < 9) ? THETA * Wc[((oc * CC + c) * 3 + t / 3) * 3 + (t % 3)]
                      : (1.0f - THETA) * We[oc * CC + c];
    unsigned short h, l;
    split2(w, h, l);
    unsigned short* gb = (unsigned short*)g_B;
    gb[(t * 2 + 0) * (64 * CPAD) + oc * CPAD + c] = h;
    gb[(t * 2 + 1) * (64 * CPAD) + oc * CPAD + c] = l;
}

// ---------------------------------------------------------------------------
// Kernel 1: HMMA implicit-GEMM conv, warp-level K-split.
// Grid (4, 256, 8), 256 threads, 2 CTA/SM.
// Warp w: p=(w>>2)&1 (px half), o=(w>>1)&1 (oc half), kh=w&1 (K half).
// Warp tile: 32 px x 32 oc x 32 K. K halves combined via smem exchange.
// ---------------------------------------------------------------------------
__global__ void __launch_bounds__(256, 2)
conv_kernel(const float* __restrict__ x,
            const float* __restrict__ b_conv,
            float* __restrict__ out) {
    extern __shared__ __align__(16) unsigned char smem[];
    __shared__ float s_red[CC];

    unsigned short* rawH = (unsigned short*)smem;
    unsigned short* rawL = (unsigned short*)(smem + RAW_PLANE_B);
    const uint32_t sbase = smem_u32(smem);
    const uint32_t sB_a  = sbase + B_OFF;

    const int tid  = threadIdx.x;
    const int lane = tid & 31;
    const int wid  = tid >> 5;
    const int x0   = blockIdx.x * PX;
    const int y    = blockIdx.y;
    const int b    = blockIdx.z;

    if (tid < CC) s_red[tid] = 0.0f;

    // ---- stage input rows y-1..y+1 as bf16 hi/lo planes, layout [r][col][c]
    const float* xb = x + (size_t)b * CC * HH * WW;
    for (int idx = tid; idx < CC * 3 * NCOL; idx += 256) {
        int c   = idx / (3 * NCOL);
        int rem = idx % (3 * NCOL);
        int r   = rem / NCOL;
        int col = rem % NCOL;
        int gy  = y - 1 + r;
        int gx  = x0 - 1 + col;
        float v = 0.0f;
        if ((unsigned)gy < HH && (unsigned)gx < WW)
            v = xb[(c * HH + gy) * WW + gx];
        unsigned short h, l;
        split2(v, h, l);
        int o = (r * NCOL + col) * CPAD + c;
        rawH[o] = h;
        rawL[o] = l;
    }
    __syncthreads();

    // ---- edge row (row 3): |x(y-1) - x(y+1)|
    for (int idx = tid; idx < NCOL * CC; idx += 256) {
        int col = idx >> 6;
        int c   = idx & 63;
        int o0 = (0 * NCOL + col) * CPAD + c;
        int o2 = (2 * NCOL + col) * CPAD + c;
        float e = fabsf(join2(rawH[o0], rawL[o0]) - join2(rawH[o2], rawL[o2]));
        unsigned short h, l;
        split2(e, h, l);
        int o3 = (3 * NCOL + col) * CPAD + c;
        rawH[o3] = h;
        rawL[o3] = l;
    }

    // ---- prefetch B tap 0
    const char* gB = (const char*)g_B;
    for (int i = tid; i < B_TAP_B / 16; i += 256)
        CP16(sB_a + i * 16, gB + i * 16);
    CP_COMMIT();

    float acc[2][4][4];
#pragma unroll
    for (int mi = 0; mi < 2; mi++)
#pragma unroll
        for (int ni = 0; ni < 4; ni++)
#pragma unroll
            for (int r = 0; r < 4; r++) acc[mi][ni][r] = 0.0f;

    const int px0 = ((wid >> 2) & 1) * 32;
    const int oc0 = ((wid >> 1) & 1) * 32;
    const int kc0 = (wid & 1) * 32;
    const int arow_lane = lane & 15;            // px row within m16
    const int acol_lane = (lane >> 4) * 8;      // k offset (mats 2,3)
    const int brow_lane = ((lane >> 4) << 3) + (lane & 7);  // oc row within n16 pair
    const int bk_lane   = ((lane >> 3) & 1) * 8;            // k offset (mats 1,3)

#pragma unroll 1
    for (int t = 0; t < 10; t++) {
        const int buf = t & 1;
        CP_WAIT0();        // tap t's B copy complete (this thread's part)
        __syncthreads();   // visibility + buffer reuse barrier

        if (t < 9) {       // prefetch tap t+1 (overlaps compute)
            const char* src = gB + (t + 1) * B_TAP_B;
            uint32_t dst = sB_a + ((t + 1) & 1) * B_TAP_B;
            for (int i = tid; i < B_TAP_B / 16; i += 256)
                CP16(dst + i * 16, src + i * 16);
            CP_COMMIT();
        }

        const int dy = (t < 9) ? t / 3 : 3;
        const int dx = (t < 9) ? t % 3 : 1;

        // A fragments: Mw=32 (2 m16), K=32 (2 k16), hi & lo planes
        uint32_t Ah[2][2][4], Al[2][2][4];
#pragma unroll
        for (int mi = 0; mi < 2; mi++) {
#pragma unroll
            for (int ki = 0; ki < 2; ki++) {
                int o = (dy * NCOL + px0 + dx + mi * 16 + arow_lane) * CPAD
                      + kc0 + ki * 16 + acol_lane;
                LDM4(Ah[mi][ki][0], Ah[mi][ki][1], Ah[mi][ki][2], Ah[mi][ki][3],
                     sbase + (uint32_t)(o * 2));
                LDM4(Al[mi][ki][0], Al[mi][ki][1], Al[mi][ki][2], Al[mi][ki][3],
                     sbase + RAW_PLANE_B + (uint32_t)(o * 2));
            }
        }

        // B fragments: Nw=32 (2 n16-pairs via x4), K=32, hi & lo planes
        const uint32_t bufH = sB_a + buf * B_TAP_B;
        const uint32_t bufL = bufH + B_PLANE_B;
        uint32_t Bh[2][2][4], Bl[2][2][4];   // [ki][nipair][4]
#pragma unroll
        for (int np = 0; np < 2; np++) {
#pragma unroll
            for (int ki = 0; ki < 2; ki++) {
                int bo = ((oc0 + np * 16 + brow_lane) * CPAD
                          + kc0 + ki * 16 + bk_lane) * 2;
                LDM4(Bh[ki][np][0], Bh[ki][np][1], Bh[ki][np][2], Bh[ki][np][3],
                     bufH + (uint32_t)bo);
                LDM4(Bl[ki][np][0], Bl[ki][np][1], Bl[ki][np][2], Bl[ki][np][3],
                     bufL + (uint32_t)bo);
            }
        }

        // 3 passes: AhBh, AhBl, AlBh
#pragma unroll
        for (int mi = 0; mi < 2; mi++)
#pragma unroll
            for (int ni = 0; ni < 4; ni++)
#pragma unroll
                for (int ki = 0; ki < 2; ki++)
                    MMA(acc[mi][ni], Ah[mi][ki], (&Bh[ki][ni >> 1][(ni & 1) * 2]));
#pragma unroll
        for (int mi = 0; mi < 2; mi++)
#pragma unroll
            for (int ni = 0; ni < 4; ni++)
#pragma unroll
                for (int ki = 0; ki < 2; ki++)
                    MMA(acc[mi][ni], Ah[mi][ki], (&Bl[ki][ni >> 1][(ni & 1) * 2]));
#pragma unroll
        for (int mi = 0; mi < 2; mi++)
#pragma unroll
            for (int ni = 0; ni < 4; ni++)
#pragma unroll
                for (int ki = 0; ki < 2; ki++)
                    MMA(acc[mi][ni], Al[mi][ki], (&Bh[ki][ni >> 1][(ni & 1) * 2]));
    }

    // ---- combine K halves via smem exchange (reuse B ring buf0 area)
    float* ex = (float*)(smem + B_OFF);
    const int pair = wid >> 1;                 // (p,o) pair 0..3
    if (wid & 1) {                             // K-half 1 warps store
#pragma unroll
        for (int mi = 0; mi < 2; mi++)
#pragma unroll
            for (int ni = 0; ni < 4; ni++)
                *(float4*)&ex[pair * 1024 + (mi * 4 + ni) * 128 + lane * 4] =
                    make_float4(acc[mi][ni][0], acc[mi][ni][1],
                                acc[mi][ni][2], acc[mi][ni][3]);
    }
    __syncthreads();

    if (!(wid & 1)) {                          // K-half 0 warps finish
#pragma unroll
        for (int mi = 0; mi < 2; mi++) {
#pragma unroll
            for (int ni = 0; ni < 4; ni++) {
                float4 p = *(float4*)&ex[pair * 1024 + (mi * 4 + ni) * 128 + lane * 4];
                const int oca = oc0 + ni * 8 + 2 * (lane & 3);
                const float ba = THETA * __ldg(&b_conv[oca]);
                const float bb = THETA * __ldg(&b_conv[oca + 1]);
                float d0 = acc[mi][ni][0] + p.x + ba;
                float d1 = acc[mi][ni][1] + p.y + bb;
                float d2 = acc[mi][ni][2] + p.z + ba;
                float d3 = acc[mi][ni][3] + p.w + bb;
                int pxg = x0 + px0 + mi * 16 + (lane >> 2);
                size_t base = ((size_t)b * CC + oca) * (size_t)(HH * WW)
                            + (size_t)y * WW + pxg;
                out[base]               = d0;
                out[base + HH * WW]     = d1;
                out[base + 8]           = d2;
                out[base + HH * WW + 8] = d3;
                float sA = d0 + d2;
                float sB = d1 + d3;
#pragma unroll
                for (int s = 4; s < 32; s <<= 1) {
                    sA += __shfl_xor_sync(0xffffffffu, sA, s);
                    sB += __shfl_xor_sync(0xffffffffu, sB, s);
                }
                if (lane < 4) {
                    atomicAdd(&s_red[oca], sA);
                    atomicAdd(&s_red[oca + 1], sB);
                }
            }
        }
    }
    __syncthreads();
    if (tid < CC) atomicAdd(&g_pooled[b * CC + tid], s_red[tid]);
}

// ---------------------------------------------------------------------------
// Kernel 2: SE attention (GAP -> 1x1 -> ReLU -> 1x1 -> sigmoid), 1 block
// ---------------------------------------------------------------------------
__global__ void attn_kernel(const float* __restrict__ W1, const float* __restrict__ b1,
                            const float* __restrict__ W2, const float* __restrict__ b2) {
    __shared__ float sh[BB * 8];
    const int t = threadIdx.x;
    if (t < BB * 8) {
        int b = t >> 3, r = t & 7;
        float s = b1[r];
        const float inv = 1.0f / (float)(HH * WW);
#pragma unroll
        for (int c = 0; c < CC; c++)
            s += (g_pooled[b * CC + c] * inv) * W1[r * CC + c];
        sh[t] = fmaxf(s, 0.0f);
    }
    __syncthreads();
    for (int idx = t; idx < BB * CC; idx += 256) {
        int b = idx >> 6, o = idx & 63;
        float s = b2[o];
#pragma unroll
        for (int r = 0; r < 8; r++)
            s += sh[b * 8 + r] * W2[o * 8 + r];
        g_attn[idx] = 1.0f / (1.0f + expf(-s));
    }
}

// ---------------------------------------------------------------------------
// Kernel 3: scale output by per-(b,c) attention (float4 grid)
// ---------------------------------------------------------------------------
__global__ void scale_kernel(float* __restrict__ out) {
    int i = blockIdx.x * blockDim.x + threadIdx.x;
    float4 v = ((float4*)out)[i];
    float a = g_attn[i >> 14];           // 16384 float4 per (b,c)
    v.x *= a; v.y *= a; v.z *= a; v.w *= a;
    ((float4*)out)[i] = v;
}

// ---------------------------------------------------------------------------
extern "C" void kernel_launch(void* const* d_in, const int* in_sizes, int n_in,
                              void* d_out, int out_size) {
    const float* x  = (const float*)d_in[0];
    const float* Wc = (const float*)d_in[1];
    const float* bc = (const float*)d_in[2];
    const float* We = (const float*)d_in[3];
    const float* W1 = (const float*)d_in[4];
    const float* b1 = (const float*)d_in[5];
    const float* W2 = (const float*)d_in[6];
    const float* b2 = (const float*)d_in[7];
    float* out = (float*)d_out;

    cudaFuncSetAttribute(conv_kernel, cudaFuncAttributeMaxDynamicSharedMemorySize, SMEM_BYTES);

    prepack_kernel<<<160, 256>>>(Wc, We);

    dim3 grid(WW / PX, HH, BB);
    conv_kernel<<<grid, 256, SMEM_BYTES>>>(x, bc, out);

    attn_kernel<<<1, 256>>>(W1, b1, W2, b2);

    scale_kernel<<<(BB * CC * HH * WW / 4) / 256, 256>>>(out);
}

// round 12
// speedup vs baseline: 2.1214x; 1.1314x over previous
#include <cuda_runtime.h>
#include <cuda_bf16.h>
#include <math.h>
#include <stdint.h>

#define BB 8
#define CC 64
#define HH 256
#define WW 256
#define THETA 0.7f

#define PX   64              // pixels per CTA
#define NCOL 66              // staged cols: x0-1 .. x0+64
#define CPAD 72              // padded channels -> 144B rows (conflict-free ldmatrix)
#define RAW_PLANE_B (4 * NCOL * CPAD * 2)       // 38016 (rows 0..2 input, row 3 = edge)
#define EX_OFF      (2 * RAW_PLANE_B)           // 76032 (K-split exchange, 16KB)
#define SMEM_BYTES  (EX_OFF + 16384)            // 92416 -> 2 CTAs/SM

__device__ float g_pooled[BB * CC];
__device__ float g_attn[BB * CC];
// B in mma-fragment order: [tap][plane][o2][k2][np][ki][lane] -> uint4 (regs m0..m3)
__device__ uint4 g_Bf[10 * 2 * 2 * 2 * 2 * 2 * 32];

// ---------------- helpers ----------------
__device__ __forceinline__ uint32_t smem_u32(const void* p) {
    uint32_t a;
    asm("{ .reg .u64 t; cvta.to.shared.u64 t, %1; cvt.u32.u64 %0, t; }" : "=r"(a) : "l"(p));
    return a;
}
#define LDM4(r0, r1, r2, r3, a) \
    asm volatile("ldmatrix.sync.aligned.m8n8.x4.shared.b16 {%0,%1,%2,%3}, [%4];" \
                 : "=r"(r0), "=r"(r1), "=r"(r2), "=r"(r3) : "r"(a))
#define MMA(c, a, b) \
    asm volatile("mma.sync.aligned.m16n8k16.row.col.f32.bf16.bf16.f32 " \
                 "{%0,%1,%2,%3},{%4,%5,%6,%7},{%8,%9},{%0,%1,%2,%3};" \
                 : "+f"((c)[0]), "+f"((c)[1]), "+f"((c)[2]), "+f"((c)[3]) \
                 : "r"((a)[0]), "r"((a)[1]), "r"((a)[2]), "r"((a)[3]), \
                   "r"((b)[0]), "r"((b)[1]))

__device__ __forceinline__ void split2(float v, unsigned short& h, unsigned short& l) {
    __nv_bfloat16 hb = __float2bfloat16(v);
    __nv_bfloat16 lb = __float2bfloat16(v - __bfloat162float(hb));
    h = __bfloat16_as_ushort(hb);
    l = __bfloat16_as_ushort(lb);
}
__device__ __forceinline__ float join2(unsigned short h, unsigned short l) {
    return __bfloat162float(__ushort_as_bfloat16(h)) + __bfloat162float(__ushort_as_bfloat16(l));
}

// ---------------------------------------------------------------------------
// Kernel 0: prepack B into mma-fragment order (prescaled, bf16 hi/lo planes).
// One thread per uint4: (tap,plane,o2,k2,np,ki,lane); reg r: oc/k per mma map.
// ---------------------------------------------------------------------------
__global__ void prepack_kernel(const float* __restrict__ Wc,
                               const float* __restrict__ We) {
    int idx = blockIdx.x * blockDim.x + threadIdx.x;   // 10240 threads
    if (idx < BB * CC) g_pooled[idx] = 0.0f;
    if (idx >= 10 * 1024) return;
    int lane  = idx & 31;
    int ki    = (idx >> 5) & 1;
    int np    = (idx >> 6) & 1;
    int k2    = (idx >> 7) & 1;
    int o2    = (idx >> 8) & 1;
    int plane = (idx >> 9) & 1;
    int tap   = idx >> 10;

    uint32_t regs[4];
#pragma unroll
    for (int r = 0; r < 4; r++) {
        int oc    = o2 * 32 + np * 16 + (r >> 1) * 8 + (lane >> 2);
        int kbase = k2 * 32 + ki * 16 + (r & 1) * 8 + 2 * (lane & 3);
        uint32_t v = 0;
#pragma unroll
        for (int e = 0; e < 2; e++) {
            int c = kbase + e;
            float w = (tap < 9)
                ? THETA * Wc[((oc * CC + c) * 3 + tap / 3) * 3 + (tap % 3)]
                : (1.0f - THETA) * We[oc * CC + c];
            unsigned short h, l;
            split2(w, h, l);
            unsigned short val = plane ? l : h;
            v |= (uint32_t)val << (e * 16);
        }
        regs[r] = v;
    }
    g_Bf[idx] = make_uint4(regs[0], regs[1], regs[2], regs[3]);
}

// ---------------------------------------------------------------------------
// Kernel 1: HMMA implicit-GEMM conv, barrier-free tap loop.
// Grid (4, 256, 8), 256 threads, 2 CTA/SM.
// Warp w: p=(w>>2)&1 px half, o=(w>>1)&1 oc half, kh=w&1 K half.
// A: ldmatrix from static raw tile. B: LDG.128 from fragment-ordered table.
// ---------------------------------------------------------------------------
__global__ void __launch_bounds__(256, 2)
conv_kernel(const float* __restrict__ x,
            const float* __restrict__ b_conv,
            float* __restrict__ out) {
    extern __shared__ __align__(16) unsigned char smem[];
    __shared__ float s_red[CC];

    unsigned short* rawH = (unsigned short*)smem;
    unsigned short* rawL = (unsigned short*)(smem + RAW_PLANE_B);
    const uint32_t sbase = smem_u32(smem);

    const int tid  = threadIdx.x;
    const int lane = tid & 31;
    const int wid  = tid >> 5;
    const int x0   = blockIdx.x * PX;
    const int y    = blockIdx.y;
    const int b    = blockIdx.z;

    if (tid < CC) s_red[tid] = 0.0f;

    // ---- stage input rows y-1..y+1 as bf16 hi/lo planes, layout [r][col][c]
    const float* xb = x + (size_t)b * CC * HH * WW;
    for (int idx = tid; idx < CC * 3 * NCOL; idx += 256) {
        int c   = idx / (3 * NCOL);
        int rem = idx % (3 * NCOL);
        int r   = rem / NCOL;
        int col = rem % NCOL;
        int gy  = y - 1 + r;
        int gx  = x0 - 1 + col;
        float v = 0.0f;
        if ((unsigned)gy < HH && (unsigned)gx < WW)
            v = xb[(c * HH + gy) * WW + gx];
        unsigned short h, l;
        split2(v, h, l);
        int o = (r * NCOL + col) * CPAD + c;
        rawH[o] = h;
        rawL[o] = l;
    }
    __syncthreads();

    // ---- edge row (row 3): |x(y-1) - x(y+1)|
    for (int idx = tid; idx < NCOL * CC; idx += 256) {
        int col = idx >> 6;
        int c   = idx & 63;
        int o0 = (0 * NCOL + col) * CPAD + c;
        int o2 = (2 * NCOL + col) * CPAD + c;
        float e = fabsf(join2(rawH[o0], rawL[o0]) - join2(rawH[o2], rawL[o2]));
        unsigned short h, l;
        split2(e, h, l);
        int o3 = (3 * NCOL + col) * CPAD + c;
        rawH[o3] = h;
        rawL[o3] = l;
    }
    __syncthreads();   // raw tile (incl. edge row) final — no more barriers until epilogue

    float acc[2][4][4];
#pragma unroll
    for (int mi = 0; mi < 2; mi++)
#pragma unroll
        for (int ni = 0; ni < 4; ni++)
#pragma unroll
            for (int r = 0; r < 4; r++) acc[mi][ni][r] = 0.0f;

    const int px0 = ((wid >> 2) & 1) * 32;
    const int oc0 = ((wid >> 1) & 1) * 32;
    const int kc0 = (wid & 1) * 32;
    const int o2w = (wid >> 1) & 1;
    const int k2w = wid & 1;
    const int arow_lane = lane & 15;
    const int acol_lane = (lane >> 4) * 8;

    // per-warp B table base: [tap][plane][o2][k2][np][ki][lane]
    const uint4* Bw = g_Bf + o2w * 256 + k2w * 128 + lane;

#pragma unroll
    for (int t = 0; t < 10; t++) {
        const int dy = (t < 9) ? t / 3 : 3;
        const int dx = (t < 9) ? t % 3 : 1;

        // B fragments via LDG.128 (fragment-ordered, L2-resident)
        uint32_t Bh[2][2][4], Bl[2][2][4];   // [ki][np][4 regs]
#pragma unroll
        for (int np = 0; np < 2; np++)
#pragma unroll
            for (int ki = 0; ki < 2; ki++) {
                uint4 vh = __ldg(Bw + t * 1024 + 0 * 512 + np * 64 + ki * 32);
                uint4 vl = __ldg(Bw + t * 1024 + 1 * 512 + np * 64 + ki * 32);
                Bh[ki][np][0] = vh.x; Bh[ki][np][1] = vh.y;
                Bh[ki][np][2] = vh.z; Bh[ki][np][3] = vh.w;
                Bl[ki][np][0] = vl.x; Bl[ki][np][1] = vl.y;
                Bl[ki][np][2] = vl.z; Bl[ki][np][3] = vl.w;
            }

        // A fragments: Mw=32 (2 m16), K=32 (2 k16), hi & lo planes
        uint32_t Ah[2][2][4], Al[2][2][4];
#pragma unroll
        for (int mi = 0; mi < 2; mi++)
#pragma unroll
            for (int ki = 0; ki < 2; ki++) {
                int o = (dy * NCOL + px0 + dx + mi * 16 + arow_lane) * CPAD
                      + kc0 + ki * 16 + acol_lane;
                LDM4(Ah[mi][ki][0], Ah[mi][ki][1], Ah[mi][ki][2], Ah[mi][ki][3],
                     sbase + (uint32_t)(o * 2));
                LDM4(Al[mi][ki][0], Al[mi][ki][1], Al[mi][ki][2], Al[mi][ki][3],
                     sbase + RAW_PLANE_B + (uint32_t)(o * 2));
            }

        // 3 passes: AhBh, AhBl, AlBh
#pragma unroll
        for (int mi = 0; mi < 2; mi++)
#pragma unroll
            for (int ni = 0; ni < 4; ni++)
#pragma unroll
                for (int ki = 0; ki < 2; ki++)
                    MMA(acc[mi][ni], Ah[mi][ki], (&Bh[ki][ni >> 1][(ni & 1) * 2]));
#pragma unroll
        for (int mi = 0; mi < 2; mi++)
#pragma unroll
            for (int ni = 0; ni < 4; ni++)
#pragma unroll
                for (int ki = 0; ki < 2; ki++)
                    MMA(acc[mi][ni], Ah[mi][ki], (&Bl[ki][ni >> 1][(ni & 1) * 2]));
#pragma unroll
        for (int mi = 0; mi < 2; mi++)
#pragma unroll
            for (int ni = 0; ni < 4; ni++)
#pragma unroll
                for (int ki = 0; ki < 2; ki++)
                    MMA(acc[mi][ni], Al[mi][ki], (&Bh[ki][ni >> 1][(ni & 1) * 2]));
    }

    // ---- combine K halves via smem exchange
    float* ex = (float*)(smem + EX_OFF);
    const int pair = wid >> 1;                 // (p,o) pair 0..3
    if (wid & 1) {                             // K-half 1 warps store
#pragma unroll
        for (int mi = 0; mi < 2; mi++)
#pragma unroll
            for (int ni = 0; ni < 4; ni++)
                *(float4*)&ex[pair * 1024 + (mi * 4 + ni) * 128 + lane * 4] =
                    make_float4(acc[mi][ni][0], acc[mi][ni][1],
                                acc[mi][ni][2], acc[mi][ni][3]);
    }
    __syncthreads();

    if (!(wid & 1)) {                          // K-half 0 warps finish
#pragma unroll
        for (int mi = 0; mi < 2; mi++) {
#pragma unroll
            for (int ni = 0; ni < 4; ni++) {
                float4 p = *(float4*)&ex[pair * 1024 + (mi * 4 + ni) * 128 + lane * 4];
                const int oca = oc0 + ni * 8 + 2 * (lane & 3);
                const float ba = THETA * __ldg(&b_conv[oca]);
                const float bb = THETA * __ldg(&b_conv[oca + 1]);
                float d0 = acc[mi][ni][0] + p.x + ba;
                float d1 = acc[mi][ni][1] + p.y + bb;
                float d2 = acc[mi][ni][2] + p.z + ba;
                float d3 = acc[mi][ni][3] + p.w + bb;
                int pxg = x0 + px0 + mi * 16 + (lane >> 2);
                size_t base = ((size_t)b * CC + oca) * (size_t)(HH * WW)
                            + (size_t)y * WW + pxg;
                out[base]               = d0;
                out[base + HH * WW]     = d1;
                out[base + 8]           = d2;
                out[base + HH * WW + 8] = d3;
                float sA = d0 + d2;
                float sB = d1 + d3;
#pragma unroll
                for (int s = 4; s < 32; s <<= 1) {
                    sA += __shfl_xor_sync(0xffffffffu, sA, s);
                    sB += __shfl_xor_sync(0xffffffffu, sB, s);
                }
                if (lane < 4) {
                    atomicAdd(&s_red[oca], sA);
                    atomicAdd(&s_red[oca + 1], sB);
                }
            }
        }
    }
    __syncthreads();
    if (tid < CC) atomicAdd(&g_pooled[b * CC + tid], s_red[tid]);
}

// ---------------------------------------------------------------------------
// Kernel 2: SE attention (GAP -> 1x1 -> ReLU -> 1x1 -> sigmoid), 1 block
// ---------------------------------------------------------------------------
__global__ void attn_kernel(const float* __restrict__ W1, const float* __restrict__ b1,
                            const float* __restrict__ W2, const float* __restrict__ b2) {
    __shared__ float sh[BB * 8];
    const int t = threadIdx.x;
    if (t < BB * 8) {
        int b = t >> 3, r = t & 7;
        float s = b1[r];
        const float inv = 1.0f / (float)(HH * WW);
#pragma unroll
        for (int c = 0; c < CC; c++)
            s += (g_pooled[b * CC + c] * inv) * W1[r * CC + c];
        sh[t] = fmaxf(s, 0.0f);
    }
    __syncthreads();
    for (int idx = t; idx < BB * CC; idx += 256) {
        int b = idx >> 6, o = idx & 63;
        float s = b2[o];
#pragma unroll
        for (int r = 0; r < 8; r++)
            s += sh[b * 8 + r] * W2[o * 8 + r];
        g_attn[idx] = 1.0f / (1.0f + expf(-s));
    }
}

// ---------------------------------------------------------------------------
// Kernel 3: scale output by per-(b,c) attention (float4 grid)
// ---------------------------------------------------------------------------
__global__ void scale_kernel(float* __restrict__ out) {
    int i = blockIdx.x * blockDim.x + threadIdx.x;
    float4 v = ((float4*)out)[i];
    float a = g_attn[i >> 14];           // 16384 float4 per (b,c)
    v.x *= a; v.y *= a; v.z *= a; v.w *= a;
    ((float4*)out)[i] = v;
}

// ---------------------------------------------------------------------------
extern "C" void kernel_launch(void* const* d_in, const int* in_sizes, int n_in,
                              void* d_out, int out_size) {
    const float* x  = (const float*)d_in[0];
    const float* Wc = (const float*)d_in[1];
    const float* bc = (const float*)d_in[2];
    const float* We = (const float*)d_in[3];
    const float* W1 = (const float*)d_in[4];
    const float* b1 = (const float*)d_in[5];
    const float* W2 = (const float*)d_in[6];
    const float* b2 = (const float*)d_in[7];
    float* out = (float*)d_out;

    cudaFuncSetAttribute(conv_kernel, cudaFuncAttributeMaxDynamicSharedMemorySize, SMEM_BYTES);

    prepack_kernel<<<40, 256>>>(Wc, We);

    dim3 grid(WW / PX, HH, BB);
    conv_kernel<<<grid, 256, SMEM_BYTES>>>(x, bc, out);

    attn_kernel<<<1, 256>>>(W1, b1, W2, b2);

    scale_kernel<<<(BB * CC * HH * WW / 4) / 256, 256>>>(out);
}

// round 13
// speedup vs baseline: 2.3798x; 1.1218x over previous
#include <cuda_runtime.h>
#include <cuda_fp16.h>
#include <math.h>
#include <stdint.h>

#define BB 8
#define CC 64
#define HH 256
#define WW 256
#define THETA 0.7f

#define PX   64              // pixels per CTA
#define NCOL 66              // staged cols: x0-1 .. x0+64
#define CPAD 72              // padded channels -> 144B rows (conflict-free ldmatrix)
#define RAW_PLANE_B (4 * NCOL * CPAD * 2)       // 38016 (rows 0..2 input, row 3 = edge)
#define EX_OFF      (2 * RAW_PLANE_B)           // 76032 (K-split exchange, 16KB)
#define SMEM_BYTES  (EX_OFF + 16384)            // 92416 -> 2 CTAs/SM

__device__ float g_pooled[BB * CC];
__device__ float g_attn[BB * CC];
// B (single fp16 plane) in mma-fragment order: [tap][o2][k2][np][ki][lane] -> uint4
__device__ uint4 g_Bf[10 * 2 * 2 * 2 * 2 * 32];

// ---------------- helpers ----------------
__device__ __forceinline__ uint32_t smem_u32(const void* p) {
    uint32_t a;
    asm("{ .reg .u64 t; cvta.to.shared.u64 t, %1; cvt.u32.u64 %0, t; }" : "=r"(a) : "l"(p));
    return a;
}
#define LDM4(r0, r1, r2, r3, a) \
    asm volatile("ldmatrix.sync.aligned.m8n8.x4.shared.b16 {%0,%1,%2,%3}, [%4];" \
                 : "=r"(r0), "=r"(r1), "=r"(r2), "=r"(r3) : "r"(a))
#define MMA(c, a, b) \
    asm volatile("mma.sync.aligned.m16n8k16.row.col.f32.f16.f16.f32 " \
                 "{%0,%1,%2,%3},{%4,%5,%6,%7},{%8,%9},{%0,%1,%2,%3};" \
                 : "+f"((c)[0]), "+f"((c)[1]), "+f"((c)[2]), "+f"((c)[3]) \
                 : "r"((a)[0]), "r"((a)[1]), "r"((a)[2]), "r"((a)[3]), \
                   "r"((b)[0]), "r"((b)[1]))

__device__ __forceinline__ void split2h(float v, unsigned short& h, unsigned short& l) {
    __half hb = __float2half_rn(v);
    __half lb = __float2half_rn(v - __half2float(hb));
    h = __half_as_ushort(hb);
    l = __half_as_ushort(lb);
}
__device__ __forceinline__ float join2h(unsigned short h, unsigned short l) {
    return __half2float(__ushort_as_half(h)) + __half2float(__ushort_as_half(l));
}

// ---------------------------------------------------------------------------
// Kernel 0: prepack B (prescaled fp16, single plane) in mma-fragment order;
// zero GAP accumulator. One thread per uint4: (tap,o2,k2,np,ki,lane).
// tap t<9: w = THETA * Wc[oc][c][t/3][t%3];  t==9: w = (1-THETA) * We[oc][c]
// ---------------------------------------------------------------------------
__global__ void prepack_kernel(const float* __restrict__ Wc,
                               const float* __restrict__ We) {
    int idx = blockIdx.x * blockDim.x + threadIdx.x;   // 6144 threads
    if (idx < BB * CC) g_pooled[idx] = 0.0f;
    if (idx >= 10 * 512) return;
    int lane = idx & 31;
    int ki   = (idx >> 5) & 1;
    int np   = (idx >> 6) & 1;
    int k2   = (idx >> 7) & 1;
    int o2   = (idx >> 8) & 1;
    int tap  = idx >> 9;

    uint32_t regs[4];
#pragma unroll
    for (int r = 0; r < 4; r++) {
        int oc    = o2 * 32 + np * 16 + (r >> 1) * 8 + (lane >> 2);
        int kbase = k2 * 32 + ki * 16 + (r & 1) * 8 + 2 * (lane & 3);
        uint32_t v = 0;
#pragma unroll
        for (int e = 0; e < 2; e++) {
            int c = kbase + e;
            float w = (tap < 9)
                ? THETA * Wc[((oc * CC + c) * 3 + tap / 3) * 3 + (tap % 3)]
                : (1.0f - THETA) * We[oc * CC + c];
            v |= (uint32_t)__half_as_ushort(__float2half_rn(w)) << (e * 16);
        }
        regs[r] = v;
    }
    g_Bf[idx] = make_uint4(regs[0], regs[1], regs[2], regs[3]);
}

// ---------------------------------------------------------------------------
// Kernel 1: HMMA implicit-GEMM conv, fp16 2-pass (Ah*B + Al*B), barrier-free
// tap loop. Grid (4, 256, 8), 256 threads, 2 CTA/SM.
// Warp w: p=(w>>2)&1 px half, o=(w>>1)&1 oc half, kh=w&1 K half.
// ---------------------------------------------------------------------------
__global__ void __launch_bounds__(256, 2)
conv_kernel(const float* __restrict__ x,
            const float* __restrict__ b_conv,
            float* __restrict__ out) {
    extern __shared__ __align__(16) unsigned char smem[];
    __shared__ float s_red[CC];

    unsigned short* rawH = (unsigned short*)smem;
    unsigned short* rawL = (unsigned short*)(smem + RAW_PLANE_B);
    const uint32_t sbase = smem_u32(smem);

    const int tid  = threadIdx.x;
    const int lane = tid & 31;
    const int wid  = tid >> 5;
    const int x0   = blockIdx.x * PX;
    const int y    = blockIdx.y;
    const int b    = blockIdx.z;

    if (tid < CC) s_red[tid] = 0.0f;

    // ---- stage input rows y-1..y+1 as fp16 hi/lo planes, layout [r][col][c]
    const float* xb = x + (size_t)b * CC * HH * WW;
    for (int idx = tid; idx < CC * 3 * NCOL; idx += 256) {
        int c   = idx / (3 * NCOL);
        int rem = idx % (3 * NCOL);
        int r   = rem / NCOL;
        int col = rem % NCOL;
        int gy  = y - 1 + r;
        int gx  = x0 - 1 + col;
        float v = 0.0f;
        if ((unsigned)gy < HH && (unsigned)gx < WW)
            v = xb[(c * HH + gy) * WW + gx];
        unsigned short h, l;
        split2h(v, h, l);
        int o = (r * NCOL + col) * CPAD + c;
        rawH[o] = h;
        rawL[o] = l;
    }
    __syncthreads();

    // ---- edge row (row 3): |x(y-1) - x(y+1)| from 22-bit staged values
    for (int idx = tid; idx < NCOL * CC; idx += 256) {
        int col = idx >> 6;
        int c   = idx & 63;
        int o0 = (0 * NCOL + col) * CPAD + c;
        int o2 = (2 * NCOL + col) * CPAD + c;
        float e = fabsf(join2h(rawH[o0], rawL[o0]) - join2h(rawH[o2], rawL[o2]));
        unsigned short h, l;
        split2h(e, h, l);
        int o3 = (3 * NCOL + col) * CPAD + c;
        rawH[o3] = h;
        rawL[o3] = l;
    }
    __syncthreads();   // raw tile final — no more barriers until epilogue

    float acc[2][4][4];
#pragma unroll
    for (int mi = 0; mi < 2; mi++)
#pragma unroll
        for (int ni = 0; ni < 4; ni++)
#pragma unroll
            for (int r = 0; r < 4; r++) acc[mi][ni][r] = 0.0f;

    const int px0 = ((wid >> 2) & 1) * 32;
    const int oc0 = ((wid >> 1) & 1) * 32;
    const int kc0 = (wid & 1) * 32;
    const int o2w = (wid >> 1) & 1;
    const int k2w = wid & 1;
    const int arow_lane = lane & 15;
    const int acol_lane = (lane >> 4) * 8;

    // per-warp B table base: [tap][o2][k2][np][ki][lane]
    const uint4* Bw = g_Bf + o2w * 256 + k2w * 128 + lane;

#pragma unroll
    for (int t = 0; t < 10; t++) {
        const int dy = (t < 9) ? t / 3 : 3;
        const int dx = (t < 9) ? t % 3 : 1;

        // B fragments via LDG.128 (fragment-ordered, L2-resident)
        uint32_t Bf[2][2][4];   // [ki][np][4 regs]
#pragma unroll
        for (int np = 0; np < 2; np++)
#pragma unroll
            for (int ki = 0; ki < 2; ki++) {
                uint4 v = __ldg(Bw + t * 512 + np * 64 + ki * 32);
                Bf[ki][np][0] = v.x; Bf[ki][np][1] = v.y;
                Bf[ki][np][2] = v.z; Bf[ki][np][3] = v.w;
            }

        // A fragments: Mw=32 (2 m16), K=32 (2 k16), hi & lo planes
        uint32_t Ah[2][2][4], Al[2][2][4];
#pragma unroll
        for (int mi = 0; mi < 2; mi++)
#pragma unroll
            for (int ki = 0; ki < 2; ki++) {
                int o = (dy * NCOL + px0 + dx + mi * 16 + arow_lane) * CPAD
                      + kc0 + ki * 16 + acol_lane;
                LDM4(Ah[mi][ki][0], Ah[mi][ki][1], Ah[mi][ki][2], Ah[mi][ki][3],
                     sbase + (uint32_t)(o * 2));
                LDM4(Al[mi][ki][0], Al[mi][ki][1], Al[mi][ki][2], Al[mi][ki][3],
                     sbase + RAW_PLANE_B + (uint32_t)(o * 2));
            }

        // 2 passes: Ah*B, Al*B
#pragma unroll
        for (int mi = 0; mi < 2; mi++)
#pragma unroll
            for (int ni = 0; ni < 4; ni++)
#pragma unroll
                for (int ki = 0; ki < 2; ki++)
                    MMA(acc[mi][ni], Ah[mi][ki], (&Bf[ki][ni >> 1][(ni & 1) * 2]));
#pragma unroll
        for (int mi = 0; mi < 2; mi++)
#pragma unroll
            for (int ni = 0; ni < 4; ni++)
#pragma unroll
                for (int ki = 0; ki < 2; ki++)
                    MMA(acc[mi][ni], Al[mi][ki], (&Bf[ki][ni >> 1][(ni & 1) * 2]));
    }

    // ---- combine K halves via smem exchange
    float* ex = (float*)(smem + EX_OFF);
    const int pair = wid >> 1;                 // (p,o) pair 0..3
    if (wid & 1) {                             // K-half 1 warps store
#pragma unroll
        for (int mi = 0; mi < 2; mi++)
#pragma unroll
            for (int ni = 0; ni < 4; ni++)
                *(float4*)&ex[pair * 1024 + (mi * 4 + ni) * 128 + lane * 4] =
                    make_float4(acc[mi][ni][0], acc[mi][ni][1],
                                acc[mi][ni][2], acc[mi][ni][3]);
    }
    __syncthreads();

    if (!(wid & 1)) {                          // K-half 0 warps finish
#pragma unroll
        for (int mi = 0; mi < 2; mi++) {
#pragma unroll
            for (int ni = 0; ni < 4; ni++) {
                float4 p = *(float4*)&ex[pair * 1024 + (mi * 4 + ni) * 128 + lane * 4];
                const int oca = oc0 + ni * 8 + 2 * (lane & 3);
                const float ba = THETA * __ldg(&b_conv[oca]);
                const float bb = THETA * __ldg(&b_conv[oca + 1]);
                float d0 = acc[mi][ni][0] + p.x + ba;
                float d1 = acc[mi][ni][1] + p.y + bb;
                float d2 = acc[mi][ni][2] + p.z + ba;
                float d3 = acc[mi][ni][3] + p.w + bb;
                int pxg = x0 + px0 + mi * 16 + (lane >> 2);
                size_t base = ((size_t)b * CC + oca) * (size_t)(HH * WW)
                            + (size_t)y * WW + pxg;
                out[base]               = d0;
                out[base + HH * WW]     = d1;
                out[base + 8]           = d2;
                out[base + HH * WW + 8] = d3;
                float sA = d0 + d2;
                float sB = d1 + d3;
#pragma unroll
                for (int s = 4; s < 32; s <<= 1) {
                    sA += __shfl_xor_sync(0xffffffffu, sA, s);
                    sB += __shfl_xor_sync(0xffffffffu, sB, s);
                }
                if (lane < 4) {
                    atomicAdd(&s_red[oca], sA);
                    atomicAdd(&s_red[oca + 1], sB);
                }
            }
        }
    }
    __syncthreads();
    if (tid < CC) atomicAdd(&g_pooled[b * CC + tid], s_red[tid]);
}

// ---------------------------------------------------------------------------
// Kernel 2: SE attention (GAP -> 1x1 -> ReLU -> 1x1 -> sigmoid), 1 block
// ---------------------------------------------------------------------------
__global__ void attn_kernel(const float* __restrict__ W1, const float* __restrict__ b1,
                            const float* __restrict__ W2, const float* __restrict__ b2) {
    __shared__ float sh[BB * 8];
    const int t = threadIdx.x;
    if (t < BB * 8) {
        int b = t >> 3, r = t & 7;
        float s = b1[r];
        const float inv = 1.0f / (float)(HH * WW);
#pragma unroll
        for (int c = 0; c < CC; c++)
            s += (g_pooled[b * CC + c] * inv) * W1[r * CC + c];
        sh[t] = fmaxf(s, 0.0f);
    }
    __syncthreads();
    for (int idx = t; idx < BB * CC; idx += 256) {
        int b = idx >> 6, o = idx & 63;
        float s = b2[o];
#pragma unroll
        for (int r = 0; r < 8; r++)
            s += sh[b * 8 + r] * W2[o * 8 + r];
        g_attn[idx] = 1.0f / (1.0f + expf(-s));
    }
}

// ---------------------------------------------------------------------------
// Kernel 3: scale output by per-(b,c) attention (float4 grid)
// ---------------------------------------------------------------------------
__global__ void scale_kernel(float* __restrict__ out) {
    int i = blockIdx.x * blockDim.x + threadIdx.x;
    float4 v = ((float4*)out)[i];
    float a = g_attn[i >> 14];           // 16384 float4 per (b,c)
    v.x *= a; v.y *= a; v.z *= a; v.w *= a;
    ((float4*)out)[i] = v;
}

// ---------------------------------------------------------------------------
extern "C" void kernel_launch(void* const* d_in, const int* in_sizes, int n_in,
                              void* d_out, int out_size) {
    const float* x  = (const float*)d_in[0];
    const float* Wc = (const float*)d_in[1];
    const float* bc = (const float*)d_in[2];
    const float* We = (const float*)d_in[3];
    const float* W1 = (const float*)d_in[4];
    const float* b1 = (const float*)d_in[5];
    const float* W2 = (const float*)d_in[6];
    const float* b2 = (const float*)d_in[7];
    float* out = (float*)d_out;

    cudaFuncSetAttribute(conv_kernel, cudaFuncAttributeMaxDynamicSharedMemorySize, SMEM_BYTES);

    prepack_kernel<<<24, 256>>>(Wc, We);

    dim3 grid(WW / PX, HH, BB);
    conv_kernel<<<grid, 256, SMEM_BYTES>>>(x, bc, out);

    attn_kernel<<<1, 256>>>(W1, b1, W2, b2);

    scale_kernel<<<(BB * CC * HH * WW / 4) / 256, 256>>>(out);
}

// round 14
// speedup vs baseline: 2.7446x; 1.1533x over previous
#include <cuda_runtime.h>
#include <cuda_fp16.h>
#include <math.h>
#include <stdint.h>

#define BB 8
#define CC 64
#define HH 256
#define WW 256
#define THETA 0.7f

#define PX   32              // pixels per CTA
#define NCOL 34              // staged cols: x0-1 .. x0+32
#define CPAD 72              // padded channels -> 144B rows (conflict-free ldmatrix)
#define RAW_PLANE_B (4 * NCOL * CPAD * 2)       // 19584 (rows 0..2 input, row 3 = edge)
#define EX_OFF      (2 * RAW_PLANE_B)           // 39168 (K-split exchange, 8KB)
#define SMEM_BYTES  (EX_OFF + 8192)             // 47360 -> 4 CTAs/SM

__device__ float g_pooled[BB * CC];
__device__ float g_attn[BB * CC];
// B (single fp16 plane) in mma-fragment order: [tap][o2][k2][np][ki][lane] -> uint4
__device__ uint4 g_Bf[10 * 2 * 2 * 2 * 2 * 32];

// ---------------- helpers ----------------
__device__ __forceinline__ uint32_t smem_u32(const void* p) {
    uint32_t a;
    asm("{ .reg .u64 t; cvta.to.shared.u64 t, %1; cvt.u32.u64 %0, t; }" : "=r"(a) : "l"(p));
    return a;
}
#define LDM4(r0, r1, r2, r3, a) \
    asm volatile("ldmatrix.sync.aligned.m8n8.x4.shared.b16 {%0,%1,%2,%3}, [%4];" \
                 : "=r"(r0), "=r"(r1), "=r"(r2), "=r"(r3) : "r"(a))
#define MMA(c, a, b) \
    asm volatile("mma.sync.aligned.m16n8k16.row.col.f32.f16.f16.f32 " \
                 "{%0,%1,%2,%3},{%4,%5,%6,%7},{%8,%9},{%0,%1,%2,%3};" \
                 : "+f"((c)[0]), "+f"((c)[1]), "+f"((c)[2]), "+f"((c)[3]) \
                 : "r"((a)[0]), "r"((a)[1]), "r"((a)[2]), "r"((a)[3]), \
                   "r"((b)[0]), "r"((b)[1]))

__device__ __forceinline__ void split2h(float v, unsigned short& h, unsigned short& l) {
    __half hb = __float2half_rn(v);
    __half lb = __float2half_rn(v - __half2float(hb));
    h = __half_as_ushort(hb);
    l = __half_as_ushort(lb);
}
__device__ __forceinline__ float join2h(unsigned short h, unsigned short l) {
    return __half2float(__ushort_as_half(h)) + __half2float(__ushort_as_half(l));
}

// ---------------------------------------------------------------------------
// Kernel 0: prepack B (prescaled fp16, single plane) in mma-fragment order;
// zero GAP accumulator. One thread per uint4: (tap,o2,k2,np,ki,lane).
// ---------------------------------------------------------------------------
__global__ void prepack_kernel(const float* __restrict__ Wc,
                               const float* __restrict__ We) {
    int idx = blockIdx.x * blockDim.x + threadIdx.x;   // 6144 threads
    if (idx < BB * CC) g_pooled[idx] = 0.0f;
    if (idx >= 10 * 512) return;
    int lane = idx & 31;
    int ki   = (idx >> 5) & 1;
    int np   = (idx >> 6) & 1;
    int k2   = (idx >> 7) & 1;
    int o2   = (idx >> 8) & 1;
    int tap  = idx >> 9;

    uint32_t regs[4];
#pragma unroll
    for (int r = 0; r < 4; r++) {
        int oc    = o2 * 32 + np * 16 + (r >> 1) * 8 + (lane >> 2);
        int kbase = k2 * 32 + ki * 16 + (r & 1) * 8 + 2 * (lane & 3);
        uint32_t v = 0;
#pragma unroll
        for (int e = 0; e < 2; e++) {
            int c = kbase + e;
            float w = (tap < 9)
                ? THETA * Wc[((oc * CC + c) * 3 + tap / 3) * 3 + (tap % 3)]
                : (1.0f - THETA) * We[oc * CC + c];
            v |= (uint32_t)__half_as_ushort(__float2half_rn(w)) << (e * 16);
        }
        regs[r] = v;
    }
    g_Bf[idx] = make_uint4(regs[0], regs[1], regs[2], regs[3]);
}

// ---------------------------------------------------------------------------
// Kernel 1: HMMA implicit-GEMM conv, fp16 2-pass, barrier-free tap loop.
// Grid (8, 256, 8), 256 threads, 4 CTAs/SM (32 warps/SM).
// Warp w: p=(w>>2)&1 px half (16), o=(w>>1)&1 oc half (32), kh=w&1 K half (32).
// ---------------------------------------------------------------------------
__global__ void __launch_bounds__(256, 4)
conv_kernel(const float* __restrict__ x,
            const float* __restrict__ b_conv,
            float* __restrict__ out) {
    extern __shared__ __align__(16) unsigned char smem[];
    __shared__ float s_red[CC];

    unsigned short* rawH = (unsigned short*)smem;
    unsigned short* rawL = (unsigned short*)(smem + RAW_PLANE_B);
    const uint32_t sbase = smem_u32(smem);

    const int tid  = threadIdx.x;
    const int lane = tid & 31;
    const int wid  = tid >> 5;
    const int x0   = blockIdx.x * PX;
    const int y    = blockIdx.y;
    const int b    = blockIdx.z;

    if (tid < CC) s_red[tid] = 0.0f;

    // ---- stage input rows y-1..y+1 as fp16 hi/lo planes, layout [r][col][c]
    const float* xb = x + (size_t)b * CC * HH * WW;
    for (int idx = tid; idx < CC * 3 * NCOL; idx += 256) {
        int c   = idx / (3 * NCOL);
        int rem = idx % (3 * NCOL);
        int r   = rem / NCOL;
        int col = rem % NCOL;
        int gy  = y - 1 + r;
        int gx  = x0 - 1 + col;
        float v = 0.0f;
        if ((unsigned)gy < HH && (unsigned)gx < WW)
            v = xb[(c * HH + gy) * WW + gx];
        unsigned short h, l;
        split2h(v, h, l);
        int o = (r * NCOL + col) * CPAD + c;
        rawH[o] = h;
        rawL[o] = l;
    }
    __syncthreads();

    // ---- edge row (row 3): |x(y-1) - x(y+1)| from staged 22-bit values
    for (int idx = tid; idx < NCOL * CC; idx += 256) {
        int col = idx >> 6;
        int c   = idx & 63;
        int o0 = (0 * NCOL + col) * CPAD + c;
        int o2 = (2 * NCOL + col) * CPAD + c;
        float e = fabsf(join2h(rawH[o0], rawL[o0]) - join2h(rawH[o2], rawL[o2]));
        unsigned short h, l;
        split2h(e, h, l);
        int o3 = (3 * NCOL + col) * CPAD + c;
        rawH[o3] = h;
        rawL[o3] = l;
    }
    __syncthreads();   // raw tile final — no more barriers until epilogue

    float acc[4][4];
#pragma unroll
    for (int ni = 0; ni < 4; ni++)
#pragma unroll
        for (int r = 0; r < 4; r++) acc[ni][r] = 0.0f;

    const int px0 = ((wid >> 2) & 1) * 16;
    const int oc0 = ((wid >> 1) & 1) * 32;
    const int kc0 = (wid & 1) * 32;
    const int o2w = (wid >> 1) & 1;
    const int k2w = wid & 1;
    const int arow_lane = lane & 15;
    const int acol_lane = (lane >> 4) * 8;

    // per-warp B table base: [tap][o2][k2][np][ki][lane]
    const uint4* Bw = g_Bf + o2w * 256 + k2w * 128 + lane;

#pragma unroll
    for (int t = 0; t < 10; t++) {
        const int dy = (t < 9) ? t / 3 : 3;
        const int dx = (t < 9) ? t % 3 : 1;

        // B fragments via LDG.128 (fragment-ordered, L2-resident)
        uint32_t Bf[2][2][4];   // [ki][np][4 regs]
#pragma unroll
        for (int np = 0; np < 2; np++)
#pragma unroll
            for (int ki = 0; ki < 2; ki++) {
                uint4 v = __ldg(Bw + t * 512 + np * 64 + ki * 32);
                Bf[ki][np][0] = v.x; Bf[ki][np][1] = v.y;
                Bf[ki][np][2] = v.z; Bf[ki][np][3] = v.w;
            }

        // A fragments: Mw=16, K=32 (2 k16), hi & lo planes
        uint32_t Ah[2][4], Al[2][4];
#pragma unroll
        for (int ki = 0; ki < 2; ki++) {
            int o = (dy * NCOL + px0 + dx + arow_lane) * CPAD
                  + kc0 + ki * 16 + acol_lane;
            LDM4(Ah[ki][0], Ah[ki][1], Ah[ki][2], Ah[ki][3],
                 sbase + (uint32_t)(o * 2));
            LDM4(Al[ki][0], Al[ki][1], Al[ki][2], Al[ki][3],
                 sbase + RAW_PLANE_B + (uint32_t)(o * 2));
        }

        // 2 passes: Ah*B, Al*B
#pragma unroll
        for (int ni = 0; ni < 4; ni++)
#pragma unroll
            for (int ki = 0; ki < 2; ki++)
                MMA(acc[ni], Ah[ki], (&Bf[ki][ni >> 1][(ni & 1) * 2]));
#pragma unroll
        for (int ni = 0; ni < 4; ni++)
#pragma unroll
            for (int ki = 0; ki < 2; ki++)
                MMA(acc[ni], Al[ki], (&Bf[ki][ni >> 1][(ni & 1) * 2]));
    }

    // ---- combine K halves via smem exchange
    float* ex = (float*)(smem + EX_OFF);
    const int pair = wid >> 1;                 // (p,o) pair 0..3
    if (wid & 1) {                             // K-half 1 warps store
#pragma unroll
        for (int ni = 0; ni < 4; ni++)
            *(float4*)&ex[pair * 512 + ni * 128 + lane * 4] =
                make_float4(acc[ni][0], acc[ni][1], acc[ni][2], acc[ni][3]);
    }
    __syncthreads();

    if (!(wid & 1)) {                          // K-half 0 warps finish
#pragma unroll
        for (int ni = 0; ni < 4; ni++) {
            float4 p = *(float4*)&ex[pair * 512 + ni * 128 + lane * 4];
            const int oca = oc0 + ni * 8 + 2 * (lane & 3);
            const float ba = THETA * __ldg(&b_conv[oca]);
            const float bb = THETA * __ldg(&b_conv[oca + 1]);
            float d0 = acc[ni][0] + p.x + ba;
            float d1 = acc[ni][1] + p.y + bb;
            float d2 = acc[ni][2] + p.z + ba;
            float d3 = acc[ni][3] + p.w + bb;
            int pxg = x0 + px0 + (lane >> 2);
            size_t base = ((size_t)b * CC + oca) * (size_t)(HH * WW)
                        + (size_t)y * WW + pxg;
            out[base]               = d0;
            out[base + HH * WW]     = d1;
            out[base + 8]           = d2;
            out[base + HH * WW + 8] = d3;
            float sA = d0 + d2;
            float sB = d1 + d3;
#pragma unroll
            for (int s = 4; s < 32; s <<= 1) {
                sA += __shfl_xor_sync(0xffffffffu, sA, s);
                sB += __shfl_xor_sync(0xffffffffu, sB, s);
            }
            if (lane < 4) {
                atomicAdd(&s_red[oca], sA);
                atomicAdd(&s_red[oca + 1], sB);
            }
        }
    }
    __syncthreads();
    if (tid < CC) atomicAdd(&g_pooled[b * CC + tid], s_red[tid]);
}

// ---------------------------------------------------------------------------
// Kernel 2: SE attention (GAP -> 1x1 -> ReLU -> 1x1 -> sigmoid), 1 block
// ---------------------------------------------------------------------------
__global__ void attn_kernel(const float* __restrict__ W1, const float* __restrict__ b1,
                            const float* __restrict__ W2, const float* __restrict__ b2) {
    __shared__ float sh[BB * 8];
    const int t = threadIdx.x;
    if (t < BB * 8) {
        int b = t >> 3, r = t & 7;
        float s = b1[r];
        const float inv = 1.0f / (float)(HH * WW);
#pragma unroll
        for (int c = 0; c < CC; c++)
            s += (g_pooled[b * CC + c] * inv) * W1[r * CC + c];
        sh[t] = fmaxf(s, 0.0f);
    }
    __syncthreads();
    for (int idx = t; idx < BB * CC; idx += 256) {
        int b = idx >> 6, o = idx & 63;
        float s = b2[o];
#pragma unroll
        for (int r = 0; r < 8; r++)
            s += sh[b * 8 + r] * W2[o * 8 + r];
        g_attn[idx] = 1.0f / (1.0f + expf(-s));
    }
}

// ---------------------------------------------------------------------------
// Kernel 3: scale output by per-(b,c) attention (float4 grid)
// ---------------------------------------------------------------------------
__global__ void scale_kernel(float* __restrict__ out) {
    int i = blockIdx.x * blockDim.x + threadIdx.x;
    float4 v = ((float4*)out)[i];
    float a = g_attn[i >> 14];           // 16384 float4 per (b,c)
    v.x *= a; v.y *= a; v.z *= a; v.w *= a;
    ((float4*)out)[i] = v;
}

// ---------------------------------------------------------------------------
extern "C" void kernel_launch(void* const* d_in, const int* in_sizes, int n_in,
                              void* d_out, int out_size) {
    const float* x  = (const float*)d_in[0];
    const float* Wc = (const float*)d_in[1];
    const float* bc = (const float*)d_in[2];
    const float* We = (const float*)d_in[3];
    const float* W1 = (const float*)d_in[4];
    const float* b1 = (const float*)d_in[5];
    const float* W2 = (const float*)d_in[6];
    const float* b2 = (const float*)d_in[7];
    float* out = (float*)d_out;

    cudaFuncSetAttribute(conv_kernel, cudaFuncAttributeMaxDynamicSharedMemorySize, SMEM_BYTES);

    prepack_kernel<<<24, 256>>>(Wc, We);

    dim3 grid(WW / PX, HH, BB);
    conv_kernel<<<grid, 256, SMEM_BYTES>>>(x, bc, out);

    attn_kernel<<<1, 256>>>(W1, b1, W2, b2);

    scale_kernel<<<(BB * CC * HH * WW / 4) / 256, 256>>>(out);
}

// round 15
// speedup vs baseline: 3.8565x; 1.4051x over previous
#include <cuda_runtime.h>
#include <cuda_fp16.h>
#include <math.h>
#include <stdint.h>

#define BB 8
#define CC 64
#define HH 256
#define WW 256
#define THETA 0.7f

#define PX   32              // pixels per CTA
#define NCOL 34              // staged cols: x0-1 .. x0+32
#define CPAD 72              // padded channels -> 144B rows (conflict-free ldmatrix)
#define RAW_B   (4 * NCOL * CPAD * 2)    // 19584: rows 0..2 input + row 3 edge, fp16
#define EX_OFF  RAW_B                    // K-split exchange (8KB)
#define SMEM_BYTES (EX_OFF + 8192)       // 27776 -> reg-limited occupancy (target 6)

__device__ float g_pooled[BB * CC];
__device__ float g_attn[BB * CC];
// B (fp16) in mma-fragment order: [tap][o2][k2][np][ki][lane] -> uint4
__device__ uint4 g_Bf[10 * 2 * 2 * 2 * 2 * 32];

// ---------------- helpers ----------------
__device__ __forceinline__ uint32_t smem_u32(const void* p) {
    uint32_t a;
    asm("{ .reg .u64 t; cvta.to.shared.u64 t, %1; cvt.u32.u64 %0, t; }" : "=r"(a) : "l"(p));
    return a;
}
#define LDM4(r0, r1, r2, r3, a) \
    asm volatile("ldmatrix.sync.aligned.m8n8.x4.shared.b16 {%0,%1,%2,%3}, [%4];" \
                 : "=r"(r0), "=r"(r1), "=r"(r2), "=r"(r3) : "r"(a))
#define MMA(c, a, b) \
    asm volatile("mma.sync.aligned.m16n8k16.row.col.f32.f16.f16.f32 " \
                 "{%0,%1,%2,%3},{%4,%5,%6,%7},{%8,%9},{%0,%1,%2,%3};" \
                 : "+f"((c)[0]), "+f"((c)[1]), "+f"((c)[2]), "+f"((c)[3]) \
                 : "r"((a)[0]), "r"((a)[1]), "r"((a)[2]), "r"((a)[3]), \
                   "r"((b)[0]), "r"((b)[1]))

// ---------------------------------------------------------------------------
// Kernel 0: prepack B (prescaled fp16) in mma-fragment order; zero GAP accum.
// tap t<9: w = THETA * Wc[oc][c][t/3][t%3];  t==9: w = (1-THETA) * We[oc][c]
// ---------------------------------------------------------------------------
__global__ void prepack_kernel(const float* __restrict__ Wc,
                               const float* __restrict__ We) {
    int idx = blockIdx.x * blockDim.x + threadIdx.x;   // 6144 threads
    if (idx < BB * CC) g_pooled[idx] = 0.0f;
    if (idx >= 10 * 512) return;
    int lane = idx & 31;
    int ki   = (idx >> 5) & 1;
    int np   = (idx >> 6) & 1;
    int k2   = (idx >> 7) & 1;
    int o2   = (idx >> 8) & 1;
    int tap  = idx >> 9;

    uint32_t regs[4];
#pragma unroll
    for (int r = 0; r < 4; r++) {
        int oc    = o2 * 32 + np * 16 + (r >> 1) * 8 + (lane >> 2);
        int kbase = k2 * 32 + ki * 16 + (r & 1) * 8 + 2 * (lane & 3);
        uint32_t v = 0;
#pragma unroll
        for (int e = 0; e < 2; e++) {
            int c = kbase + e;
            float w = (tap < 9)
                ? THETA * Wc[((oc * CC + c) * 3 + tap / 3) * 3 + (tap % 3)]
                : (1.0f - THETA) * We[oc * CC + c];
            v |= (uint32_t)__half_as_ushort(__float2half_rn(w)) << (e * 16);
        }
        regs[r] = v;
    }
    g_Bf[idx] = make_uint4(regs[0], regs[1], regs[2], regs[3]);
}

// ---------------------------------------------------------------------------
// Kernel 1: HMMA implicit-GEMM conv, single-pass fp16, barrier-free tap loop.
// Grid (8, 256, 8), 256 threads, target 6 CTAs/SM (48 warps).
// Warp w: p=(w>>2)&1 px half (16), o=(w>>1)&1 oc half (32), kh=w&1 K half (32).
// ---------------------------------------------------------------------------
__global__ void __launch_bounds__(256, 6)
conv_kernel(const float* __restrict__ x,
            const float* __restrict__ b_conv,
            float* __restrict__ out) {
    extern __shared__ __align__(16) unsigned char smem[];
    __shared__ float s_red[CC];

    unsigned short* raw = (unsigned short*)smem;
    const uint32_t sbase = smem_u32(smem);

    const int tid  = threadIdx.x;
    const int lane = tid & 31;
    const int wid  = tid >> 5;
    const int x0   = blockIdx.x * PX;
    const int y    = blockIdx.y;
    const int b    = blockIdx.z;

    if (tid < CC) s_red[tid] = 0.0f;

    // ---- stage input rows y-1..y+1 as fp16, layout [r][col][c]
    const float* xb = x + (size_t)b * CC * HH * WW;
    for (int idx = tid; idx < CC * 3 * NCOL; idx += 256) {
        int c   = idx / (3 * NCOL);
        int rem = idx % (3 * NCOL);
        int r   = rem / NCOL;
        int col = rem % NCOL;
        int gy  = y - 1 + r;
        int gx  = x0 - 1 + col;
        float v = 0.0f;
        if ((unsigned)gy < HH && (unsigned)gx < WW)
            v = xb[(c * HH + gy) * WW + gx];
        raw[(r * NCOL + col) * CPAD + c] = __half_as_ushort(__float2half_rn(v));
    }
    __syncthreads();

    // ---- edge row (row 3): |x(y-1) - x(y+1)| from staged fp16 values
    for (int idx = tid; idx < NCOL * CC; idx += 256) {
        int col = idx >> 6;
        int c   = idx & 63;
        float a0 = __half2float(__ushort_as_half(raw[(0 * NCOL + col) * CPAD + c]));
        float a2 = __half2float(__ushort_as_half(raw[(2 * NCOL + col) * CPAD + c]));
        raw[(3 * NCOL + col) * CPAD + c] =
            __half_as_ushort(__float2half_rn(fabsf(a0 - a2)));
    }
    __syncthreads();   // raw tile final — no more barriers until epilogue

    float acc[4][4];
#pragma unroll
    for (int ni = 0; ni < 4; ni++)
#pragma unroll
        for (int r = 0; r < 4; r++) acc[ni][r] = 0.0f;

    const int px0 = ((wid >> 2) & 1) * 16;
    const int oc0 = ((wid >> 1) & 1) * 32;
    const int kc0 = (wid & 1) * 32;
    const int o2w = (wid >> 1) & 1;
    const int k2w = wid & 1;
    const int arow_lane = lane & 15;
    const int acol_lane = (lane >> 4) * 8;

    // per-warp B table base: [tap][o2][k2][np][ki][lane]
    const uint4* Bw = g_Bf + o2w * 256 + k2w * 128 + lane;

#pragma unroll
    for (int t = 0; t < 10; t++) {
        const int dy = (t < 9) ? t / 3 : 3;
        const int dx = (t < 9) ? t % 3 : 1;

        // ki-interleaved to keep live set small: A(ki) 4 regs + B(ki) 8 regs
#pragma unroll
        for (int ki = 0; ki < 2; ki++) {
            uint32_t A[4];
            int o = (dy * NCOL + px0 + dx + arow_lane) * CPAD
                  + kc0 + ki * 16 + acol_lane;
            LDM4(A[0], A[1], A[2], A[3], sbase + (uint32_t)(o * 2));

            uint32_t Bf[2][4];
#pragma unroll
            for (int np = 0; np < 2; np++) {
                uint4 v = __ldg(Bw + t * 512 + np * 64 + ki * 32);
                Bf[np][0] = v.x; Bf[np][1] = v.y;
                Bf[np][2] = v.z; Bf[np][3] = v.w;
            }
#pragma unroll
            for (int ni = 0; ni < 4; ni++)
                MMA(acc[ni], A, (&Bf[ni >> 1][(ni & 1) * 2]));
        }
    }

    // ---- combine K halves via smem exchange
    float* ex = (float*)(smem + EX_OFF);
    const int pair = wid >> 1;                 // (p,o) pair 0..3
    if (wid & 1) {                             // K-half 1 warps store
#pragma unroll
        for (int ni = 0; ni < 4; ni++)
            *(float4*)&ex[pair * 512 + ni * 128 + lane * 4] =
                make_float4(acc[ni][0], acc[ni][1], acc[ni][2], acc[ni][3]);
    }
    __syncthreads();

    if (!(wid & 1)) {                          // K-half 0 warps finish
#pragma unroll
        for (int ni = 0; ni < 4; ni++) {
            float4 p = *(float4*)&ex[pair * 512 + ni * 128 + lane * 4];
            const int oca = oc0 + ni * 8 + 2 * (lane & 3);
            const float ba = THETA * __ldg(&b_conv[oca]);
            const float bb = THETA * __ldg(&b_conv[oca + 1]);
            float d0 = acc[ni][0] + p.x + ba;
            float d1 = acc[ni][1] + p.y + bb;
            float d2 = acc[ni][2] + p.z + ba;
            float d3 = acc[ni][3] + p.w + bb;
            int pxg = x0 + px0 + (lane >> 2);
            size_t base = ((size_t)b * CC + oca) * (size_t)(HH * WW)
                        + (size_t)y * WW + pxg;
            out[base]               = d0;
            out[base + HH * WW]     = d1;
            out[base + 8]           = d2;
            out[base + HH * WW + 8] = d3;
            float sA = d0 + d2;
            float sB = d1 + d3;
#pragma unroll
            for (int s = 4; s < 32; s <<= 1) {
                sA += __shfl_xor_sync(0xffffffffu, sA, s);
                sB += __shfl_xor_sync(0xffffffffu, sB, s);
            }
            if (lane < 4) {
                atomicAdd(&s_red[oca], sA);
                atomicAdd(&s_red[oca + 1], sB);
            }
        }
    }
    __syncthreads();
    if (tid < CC) atomicAdd(&g_pooled[b * CC + tid], s_red[tid]);
}

// ---------------------------------------------------------------------------
// Kernel 2: SE attention (GAP -> 1x1 -> ReLU -> 1x1 -> sigmoid), 1 block
// ---------------------------------------------------------------------------
__global__ void attn_kernel(const float* __restrict__ W1, const float* __restrict__ b1,
                            const float* __restrict__ W2, const float* __restrict__ b2) {
    __shared__ float sh[BB * 8];
    const int t = threadIdx.x;
    if (t < BB * 8) {
        int b = t >> 3, r = t & 7;
        float s = b1[r];
        const float inv = 1.0f / (float)(HH * WW);
#pragma unroll
        for (int c = 0; c < CC; c++)
            s += (g_pooled[b * CC + c] * inv) * W1[r * CC + c];
        sh[t] = fmaxf(s, 0.0f);
    }
    __syncthreads();
    for (int idx = t; idx < BB * CC; idx += 256) {
        int b = idx >> 6, o = idx & 63;
        float s = b2[o];
#pragma unroll
        for (int r = 0; r < 8; r++)
            s += sh[b * 8 + r] * W2[o * 8 + r];
        g_attn[idx] = 1.0f / (1.0f + expf(-s));
    }
}

// ---------------------------------------------------------------------------
// Kernel 3: scale output by per-(b,c) attention (float4 grid)
// ---------------------------------------------------------------------------
__global__ void scale_kernel(float* __restrict__ out) {
    int i = blockIdx.x * blockDim.x + threadIdx.x;
    float4 v = ((float4*)out)[i];
    float a = g_attn[i >> 14];           // 16384 float4 per (b,c)
    v.x *= a; v.y *= a; v.z *= a; v.w *= a;
    ((float4*)out)[i] = v;
}

// ---------------------------------------------------------------------------
extern "C" void kernel_launch(void* const* d_in, const int* in_sizes, int n_in,
                              void* d_out, int out_size) {
    const float* x  = (const float*)d_in[0];
    const float* Wc = (const float*)d_in[1];
    const float* bc = (const float*)d_in[2];
    const float* We = (const float*)d_in[3];
    const float* W1 = (const float*)d_in[4];
    const float* b1 = (const float*)d_in[5];
    const float* W2 = (const float*)d_in[6];
    const float* b2 = (const float*)d_in[7];
    float* out = (float*)d_out;

    cudaFuncSetAttribute(conv_kernel, cudaFuncAttributeMaxDynamicSharedMemorySize, SMEM_BYTES);

    prepack_kernel<<<24, 256>>>(Wc, We);

    dim3 grid(WW / PX, HH, BB);
    conv_kernel<<<grid, 256, SMEM_BYTES>>>(x, bc, out);

    attn_kernel<<<1, 256>>>(W1, b1, W2, b2);

    scale_kernel<<<(BB * CC * HH * WW / 4) / 256, 256>>>(out);
}